// round 9
// baseline (speedup 1.0000x reference)
#include <cuda_runtime.h>
#include <cuda_bf16.h>
#include <math.h>

// Problem dims
#define Bq   128
#define Sq   256
#define Eq   512
#define Hq   1024
#define Vq   2048
#define G4H  4096   // 4*H
#define Kout 2048   // 2*H (output GEMM K)
#define Mout (Bq * Sq)

// ---------------------------------------------------------------------------
// Scratch (device globals; no allocation allowed)
// ---------------------------------------------------------------------------
__device__ float g_Wtf[Eq * G4H];            //  8 MB: Wf gate-interleaved
__device__ float g_Wtb[Eq * G4H];
__device__ float g_btf[G4H];
__device__ float g_btb[G4H];
__device__ float g_embWtf[Vq * G4H];         // 32 MB (bias folded)
__device__ float g_embWtb[Vq * G4H];
__device__ float g_c[2][Bq * Hq];            // [dir] cell state (fp32)
__device__ unsigned g_barrier[4];            // per-(b-half, dir) step barrier
// Recurrent weights, split-bf16, gate-interleaved, TRANSPOSED: [n=j*4+g][k]
__device__ __nv_bfloat16 g_Uhif[G4H * Hq];   // 8 MB
__device__ __nv_bfloat16 g_Ulof[G4H * Hq];
__device__ __nv_bfloat16 g_Uhib[G4H * Hq];
__device__ __nv_bfloat16 g_Ulob[G4H * Hq];
// hcat as split-bf16; row m = b*S+s, col = dir*H+j. ALSO the A operand of the
// next recurrent step (rows at s_prev) and of the output GEMM.
__device__ __nv_bfloat16 g_Ahi[(size_t)Mout * Kout]; // 128 MB
__device__ __nv_bfloat16 g_Alo[(size_t)Mout * Kout]; // 128 MB
// Wd transposed + split: B[n][k] = Wd[k][n]
__device__ __nv_bfloat16 g_Bhi[Vq * Kout];   // 8 MB
__device__ __nv_bfloat16 g_Blo[Vq * Kout];   // 8 MB

// ---------------------------------------------------------------------------
// f32x2 packed-FMA helpers (embW precompute GEMM)
// ---------------------------------------------------------------------------
__device__ __forceinline__ unsigned long long dup2(float x) {
    unsigned long long r;
    asm("mov.b64 %0, {%1, %1};" : "=l"(r) : "f"(x));
    return r;
}
__device__ __forceinline__ void ffma2(unsigned long long &acc,
                                      unsigned long long a,
                                      unsigned long long b) {
    asm("fma.rn.f32x2 %0, %1, %2, %0;" : "+l"(acc) : "l"(a), "l"(b));
}
__device__ __forceinline__ float2 unpack2(unsigned long long v) {
    float2 f;
    asm("mov.b64 {%0, %1}, %2;" : "=f"(f.x), "=f"(f.y) : "l"(v));
    return f;
}
__device__ __forceinline__ float sigmoidf_fast(float x) {
    return __fdividef(1.f, 1.f + __expf(-x));
}
__device__ __forceinline__ unsigned smem_to_u32(const void* p) {
    unsigned a;
    asm("{ .reg .u64 t; cvta.to.shared.u64 t, %1; cvt.u32.u64 %0, t; }"
        : "=r"(a) : "l"(p));
    return a;
}

// ---------------------------------------------------------------------------
// sm_80+ portable async-copy + ldmatrix + HMMA
// ---------------------------------------------------------------------------
__device__ __forceinline__ void cp_async16(unsigned smem_addr, const void* gptr) {
    asm volatile("cp.async.cg.shared.global [%0], [%1], 16;"
                 :: "r"(smem_addr), "l"(gptr));
}
#define CP_COMMIT() asm volatile("cp.async.commit_group;" ::: "memory")
#define CP_WAIT(n)  asm volatile("cp.async.wait_group %0;" :: "n"(n) : "memory")

__device__ __forceinline__ void ldmatrix_x4(unsigned* r, unsigned addr) {
    asm volatile("ldmatrix.sync.aligned.m8n8.x4.shared.b16 {%0,%1,%2,%3}, [%4];"
                 : "=r"(r[0]), "=r"(r[1]), "=r"(r[2]), "=r"(r[3]) : "r"(addr));
}
__device__ __forceinline__ void mma_bf16(float* c, const unsigned* a,
                                         const unsigned* b) {
    asm volatile(
        "mma.sync.aligned.m16n8k16.row.col.f32.bf16.bf16.f32 "
        "{%0,%1,%2,%3}, {%4,%5,%6,%7}, {%8,%9}, {%0,%1,%2,%3};"
        : "+f"(c[0]), "+f"(c[1]), "+f"(c[2]), "+f"(c[3])
        : "r"(a[0]), "r"(a[1]), "r"(a[2]), "r"(a[3]), "r"(b[0]), "r"(b[1]));
}

// ---------------------------------------------------------------------------
// Zero the cell state + step barriers
// ---------------------------------------------------------------------------
__global__ void init_state_kernel() {
    int i = blockIdx.x * blockDim.x + threadIdx.x;
    if (i < Bq * Hq) { g_c[0][i] = 0.f; g_c[1][i] = 0.f; }
    if (i < 4) g_barrier[i] = 0u;
}

// ---------------------------------------------------------------------------
// Gate-interleave W, b:  Wt[e][j*4+g] = W[e][g*H+j]
// ---------------------------------------------------------------------------
__global__ void interleave_W_kernel(const float* __restrict__ Wf,
                                    const float* __restrict__ Wb,
                                    const float* __restrict__ bf,
                                    const float* __restrict__ bb) {
    int idx = blockIdx.x * blockDim.x + threadIdx.x;
    if (idx < Eq * G4H) {
        int e = idx >> 12;
        int c = idx & 4095;
        int src = e * G4H + (c & 3) * Hq + (c >> 2);
        g_Wtf[idx] = Wf[src];
        g_Wtb[idx] = Wb[src];
    }
    if (idx < G4H) {
        int src = (idx & 3) * Hq + (idx >> 2);
        g_btf[idx] = bf[src];
        g_btb[idx] = bb[src];
    }
}

// ---------------------------------------------------------------------------
// Split + transpose + gate-interleave U:
//   Uhi/Ulo[dir][(j*4+g)][k] = split_bf16(U[k][g*H+j])
// ---------------------------------------------------------------------------
__global__ void split_transpose_U_kernel(const float* __restrict__ Uf,
                                         const float* __restrict__ Ub) {
    __shared__ float ts[32][33];
    int j0 = blockIdx.x * 32;
    int k0 = blockIdx.y * 32;
    int g   = blockIdx.z & 3;
    int dir = blockIdx.z >> 2;
    const float* U = dir ? Ub : Uf;
    __nv_bfloat16* Dhi = dir ? g_Uhib : g_Uhif;
    __nv_bfloat16* Dlo = dir ? g_Ulob : g_Ulof;
    int tx = threadIdx.x, ty = threadIdx.y;
#pragma unroll
    for (int i = 0; i < 32; i += 8)
        ts[ty + i][tx] = U[(size_t)(k0 + ty + i) * G4H + g * Hq + j0 + tx];
    __syncthreads();
#pragma unroll
    for (int i = 0; i < 32; i += 8) {
        int j = j0 + ty + i;
        float v = ts[tx][ty + i];          // U[k0+tx][g*H + j]
        __nv_bfloat16 hi = __float2bfloat16(v);
        float rem = v - __bfloat162float(hi);
        size_t o = (size_t)((j << 2) + g) * Hq + k0 + tx;
        Dhi[o] = hi;
        Dlo[o] = __float2bfloat16(rem);
    }
}

// ---------------------------------------------------------------------------
// Transpose + split Wd:  Bhi/Blo[n][k] = split_bf16(Wd[k][n])
// ---------------------------------------------------------------------------
__global__ void split_transpose_Wd_kernel(const float* __restrict__ Wd) {
    __shared__ float ts[32][33];
    int n0 = blockIdx.x * 32;
    int k0 = blockIdx.y * 32;
    int tx = threadIdx.x, ty = threadIdx.y;
#pragma unroll
    for (int i = 0; i < 32; i += 8)
        ts[ty + i][tx] = Wd[(size_t)(k0 + ty + i) * Vq + n0 + tx];
    __syncthreads();
#pragma unroll
    for (int i = 0; i < 32; i += 8) {
        float v = ts[tx][ty + i];            // Wd[k0+tx][n0+ty+i]
        __nv_bfloat16 hi = __float2bfloat16(v);
        float rem = v - __bfloat162float(hi);
        size_t o = (size_t)(n0 + ty + i) * Kout + k0 + tx;
        g_Bhi[o] = hi;
        g_Blo[o] = __float2bfloat16(rem);
    }
}

// ---------------------------------------------------------------------------
// Generic tiled fp32 GEMM (embW precompute):  C = A @ B + bias
// ---------------------------------------------------------------------------
__global__ __launch_bounds__(256) void gemm_bias_kernel(
    const float* __restrict__ A, const float* __restrict__ B,
    const float* __restrict__ bias, float* __restrict__ C,
    int M, int N, int K)
{
    __shared__ float As[16][128];
    __shared__ float Bs[16][128];

    const int tid = threadIdx.x;
    const int n0  = blockIdx.x * 128;
    const int m0  = blockIdx.y * 128;

    const int a_kq = tid & 3;
    const int a_r  = tid >> 2;
    const int b_c4 = tid & 31;
    const int b_k  = tid >> 5;

    const int trow = tid >> 4;
    const int tcol = tid & 15;

    unsigned long long acc[4][8];
#pragma unroll
    for (int i = 0; i < 4; i++)
#pragma unroll
        for (int j = 0; j < 8; j++) acc[i][j] = 0ull;

    float4 pa0, pa1, pb0, pb1;
    pa0 = *reinterpret_cast<const float4*>(&A[(m0 + a_r)      * K + a_kq * 4]);
    pa1 = *reinterpret_cast<const float4*>(&A[(m0 + a_r + 64) * K + a_kq * 4]);
    pb0 = *reinterpret_cast<const float4*>(&B[(b_k)     * N + n0 + b_c4 * 4]);
    pb1 = *reinterpret_cast<const float4*>(&B[(b_k + 8) * N + n0 + b_c4 * 4]);

    for (int kc = 0; kc < K; kc += 16) {
        As[a_kq * 4 + 0][a_r] = pa0.x;
        As[a_kq * 4 + 1][a_r] = pa0.y;
        As[a_kq * 4 + 2][a_r] = pa0.z;
        As[a_kq * 4 + 3][a_r] = pa0.w;
        As[a_kq * 4 + 0][a_r + 64] = pa1.x;
        As[a_kq * 4 + 1][a_r + 64] = pa1.y;
        As[a_kq * 4 + 2][a_r + 64] = pa1.z;
        As[a_kq * 4 + 3][a_r + 64] = pa1.w;
        *reinterpret_cast<float4*>(&Bs[b_k][b_c4 * 4])     = pb0;
        *reinterpret_cast<float4*>(&Bs[b_k + 8][b_c4 * 4]) = pb1;
        __syncthreads();

        const int kn = kc + 16;
        if (kn < K) {
            pa0 = *reinterpret_cast<const float4*>(&A[(m0 + a_r)      * K + kn + a_kq * 4]);
            pa1 = *reinterpret_cast<const float4*>(&A[(m0 + a_r + 64) * K + kn + a_kq * 4]);
            pb0 = *reinterpret_cast<const float4*>(&B[(kn + b_k)     * N + n0 + b_c4 * 4]);
            pb1 = *reinterpret_cast<const float4*>(&B[(kn + b_k + 8) * N + n0 + b_c4 * 4]);
        }

#pragma unroll
        for (int k = 0; k < 16; k++) {
            const ulonglong2* ap =
                reinterpret_cast<const ulonglong2*>(&As[k][trow * 8]);
            ulonglong2 av0 = ap[0];
            ulonglong2 av1 = ap[1];
            unsigned long long a4[4] = {av0.x, av0.y, av1.x, av1.y};

            float4 bv0 = *reinterpret_cast<const float4*>(&Bs[k][tcol * 8]);
            float4 bv1 = *reinterpret_cast<const float4*>(&Bs[k][tcol * 8 + 4]);
            unsigned long long bd[8];
            bd[0] = dup2(bv0.x); bd[1] = dup2(bv0.y);
            bd[2] = dup2(bv0.z); bd[3] = dup2(bv0.w);
            bd[4] = dup2(bv1.x); bd[5] = dup2(bv1.y);
            bd[6] = dup2(bv1.z); bd[7] = dup2(bv1.w);

#pragma unroll
            for (int ip = 0; ip < 4; ip++)
#pragma unroll
                for (int j = 0; j < 8; j++)
                    ffma2(acc[ip][j], a4[ip], bd[j]);
        }
        __syncthreads();
    }

    float bsv[8];
#pragma unroll
    for (int j = 0; j < 8; j++) bsv[j] = bias[n0 + tcol * 8 + j];

#pragma unroll
    for (int ip = 0; ip < 4; ip++) {
        float2 v[8];
#pragma unroll
        for (int j = 0; j < 8; j++) v[j] = unpack2(acc[ip][j]);
        int r0 = m0 + trow * 8 + ip * 2;
        float* c0 = C + (size_t)r0 * N + n0 + tcol * 8;
        float* c1 = c0 + N;
        float4 x0 = make_float4(v[0].x + bsv[0], v[1].x + bsv[1],
                                v[2].x + bsv[2], v[3].x + bsv[3]);
        float4 x1 = make_float4(v[4].x + bsv[4], v[5].x + bsv[5],
                                v[6].x + bsv[6], v[7].x + bsv[7]);
        float4 y0 = make_float4(v[0].y + bsv[0], v[1].y + bsv[1],
                                v[2].y + bsv[2], v[3].y + bsv[3]);
        float4 y1 = make_float4(v[4].y + bsv[4], v[5].y + bsv[5],
                                v[6].y + bsv[6], v[7].y + bsv[7]);
        *reinterpret_cast<float4*>(c0)     = x0;
        *reinterpret_cast<float4*>(c0 + 4) = x1;
        *reinterpret_cast<float4*>(c1)     = y0;
        *reinterpret_cast<float4*>(c1 + 4) = y1;
    }
}

// ---------------------------------------------------------------------------
// PERSISTENT recurrence kernel: all 256 steps in ONE launch.
// Grid (32, 2, 2) = 128 CTAs, 512 threads -> 1 CTA/SM, all wave-1 resident.
// CTA (x, y, z) produces h rows [64y,64y+64) x cols [32x,32x+32) of dir z and
// consumes h rows [64y,64y+64) x ALL cols of dir z -> sync group = (y, z):
// four independent 32-CTA barriers (monotonic counters in g_barrier).
// GEMM body identical to R7 (validated): 3-pass split-bf16 HMMA, BK=32,
// 2-stage cp.async pipeline, warp tile 16x32.
// ---------------------------------------------------------------------------
#define LS_RS     80                       // bytes per 32-bf16 SMEM row
#define LS_ATILE  (64 * LS_RS)             // 5120
#define LS_BTILE  (128 * LS_RS)            // 10240
#define LS_STAGE  (2 * LS_ATILE + 2 * LS_BTILE)  // 30720
#define LS_SMEM   (2 * LS_STAGE)           // 61440 (z-tile aliases this)

__global__ __launch_bounds__(512, 1) void lstm_persistent_kernel(
    const int* __restrict__ tokens)
{
    extern __shared__ char smem[];
    const unsigned sb = smem_to_u32(smem);
    float (*zs)[132] = reinterpret_cast<float (*)[132]>(smem);  // 64x132 fp32
    __shared__ int toks[64];

    const int tid = threadIdx.x;
    const int wid = tid >> 5;
    const int lane = tid & 31;
    const int warp_m = wid >> 2;        // 0..3 (16 rows each)
    const int warp_n = wid & 3;         // 0..3 (32 cols each)
    const int c0  = blockIdx.x * 128;   // interleaved col base
    const int b0  = blockIdx.y * 64;
    const int dir = blockIdx.z;
    const int gid = blockIdx.y * 2 + blockIdx.z;   // barrier group

    const __nv_bfloat16* Uhi = dir ? g_Uhib : g_Uhif;
    const __nv_bfloat16* Ulo = dir ? g_Ulob : g_Ulof;
    const float* embW = dir ? g_embWtb : g_embWtf;
    float* cptr = &g_c[dir][0];
    const int j0q = c0 >> 2;

    for (int t = 0; t < Sq; t++) {
        const int s  = dir ? (Sq - 1 - t) : t;
        const int sp = dir ? (Sq - t) : (t - 1);   // previous step's s (t>0)

        if (tid < 64) toks[tid] = tokens[(b0 + tid) * Sq + s];

        float acc[4][4];                    // [nt][quad]
#pragma unroll
        for (int nt = 0; nt < 4; nt++)
#pragma unroll
            for (int q = 0; q < 4; q++) acc[nt][q] = 0.f;

        if (t > 0) {
            auto issue_chunk = [&](int kc, int buf) {
                const unsigned bb = sb + buf * LS_STAGE;
#pragma unroll
                for (int i = 0; i < 3; i++) {
                    int id = i * 512 + tid;            // 0..1535
                    if (id < 512) {
                        int part = id >> 8;            // 0 = Ahi, 1 = Alo
                        int rem = id & 255;
                        int r = rem >> 2, ch = rem & 3;
                        const __nv_bfloat16* src = part ? g_Alo : g_Ahi;
                        unsigned dst = bb + part * LS_ATILE + r * LS_RS + ch * 16;
                        cp_async16(dst, src +
                            ((size_t)(b0 + r) * Sq + sp) * Kout + dir * Hq + kc + ch * 8);
                    } else {
                        int id2 = id - 512;            // 0..1023
                        int part = id2 >> 9;           // 0 = Uhi, 1 = Ulo
                        int rem = id2 & 511;
                        int r = rem >> 2, ch = rem & 3;
                        const __nv_bfloat16* src = part ? Ulo : Uhi;
                        unsigned dst = bb + 2 * LS_ATILE + part * LS_BTILE +
                                       r * LS_RS + ch * 16;
                        cp_async16(dst, src + (size_t)(c0 + r) * Hq + kc + ch * 8);
                    }
                }
                CP_COMMIT();
            };

            issue_chunk(0, 0);
            issue_chunk(32, 1);

            for (int c = 0; c < 32; c++) {
                if (c < 31) { CP_WAIT(1); } else { CP_WAIT(0); }
                __syncthreads();

                const unsigned bb  = sb + (c & 1) * LS_STAGE;
                const unsigned sAh = bb;
                const unsigned sAl = bb + LS_ATILE;
                const unsigned sBh = bb + 2 * LS_ATILE;
                const unsigned sBl = bb + 2 * LS_ATILE + LS_BTILE;

#pragma unroll
                for (int kh = 0; kh < 2; kh++) {
                    const int koff = kh * 32;          // bytes (16 bf16)
                    const unsigned a_off =
                        (warp_m * 16 + (lane & 15)) * LS_RS + koff + ((lane >> 4) << 4);
                    const unsigned b_off =
                        (warp_n * 32 + (lane & 7) + ((lane >> 4) << 3)) * LS_RS +
                        koff + (((lane >> 3) & 1) << 4);

                    unsigned aH[4], aL[4], bH[4][2], bL[4][2];
                    ldmatrix_x4(aH, sAh + a_off);
                    ldmatrix_x4(aL, sAl + a_off);
#pragma unroll
                    for (int np = 0; np < 2; np++) {
                        unsigned r4[4];
                        ldmatrix_x4(r4, sBh + b_off + np * 16 * LS_RS);
                        bH[np * 2][0] = r4[0]; bH[np * 2][1] = r4[1];
                        bH[np * 2 + 1][0] = r4[2]; bH[np * 2 + 1][1] = r4[3];
                        ldmatrix_x4(r4, sBl + b_off + np * 16 * LS_RS);
                        bL[np * 2][0] = r4[0]; bL[np * 2][1] = r4[1];
                        bL[np * 2 + 1][0] = r4[2]; bL[np * 2 + 1][1] = r4[3];
                    }

#pragma unroll
                    for (int nt = 0; nt < 4; nt++) {
                        mma_bf16(acc[nt], aH, bH[nt]);
                        mma_bf16(acc[nt], aH, bL[nt]);
                        mma_bf16(acc[nt], aL, bH[nt]);
                    }
                }

                __syncthreads();
                if (c + 2 < 32) issue_chunk((c + 2) * 32, c & 1);
            }
        }

        __syncthreads();   // all MMA reads done; safe to alias stage smem as zs

        // fragments -> z tile
        {
            int r = warp_m * 16 + (lane >> 2);
#pragma unroll
            for (int nt = 0; nt < 4; nt++) {
                int col = warp_n * 32 + nt * 8 + 2 * (lane & 3);
                *reinterpret_cast<float2*>(&zs[r][col]) =
                    make_float2(acc[nt][0], acc[nt][1]);
                *reinterpret_cast<float2*>(&zs[r + 8][col]) =
                    make_float2(acc[nt][2], acc[nt][3]);
            }
        }
        __syncthreads();

        // fused gate update: 64 rows x 32 hidden units = 2048 items / 512 thr
#pragma unroll
        for (int it = 0; it < 4; it++) {
            int idx = it * 512 + tid;
            int r  = idx >> 5;     // 0..63
            int jj = idx & 31;     // 0..31
            int j = j0q + jj;

            float4 z4 = *reinterpret_cast<const float4*>(&zs[r][jj * 4]);
            int tok = toks[r];
            float4 ew = *reinterpret_cast<const float4*>(
                &embW[(size_t)tok * G4H + (j << 2)]);
            float zi = z4.x + ew.x;
            float zf = z4.y + ew.y;
            float zg = z4.z + ew.z;
            float zo = z4.w + ew.w;

            float ig = sigmoidf_fast(zi);
            float fg = sigmoidf_fast(zf);
            float og = sigmoidf_fast(zo);
            float gg = dir ? fmaxf(zg, 0.f) : tanhf(zg);

            int ci = (b0 + r) * Hq + j;
            float cv = fg * cptr[ci] + ig * gg;
            cptr[ci] = cv;
            float hc = dir ? fmaxf(cv, 0.f) : tanhf(cv);
            float hv = og * hc;

            size_t ao = ((size_t)(b0 + r) * Sq + s) * Kout + dir * Hq + j;
            __nv_bfloat16 hi = __float2bfloat16(hv);
            g_Ahi[ao] = hi;
            g_Alo[ao] = __float2bfloat16(hv - __bfloat162float(hi));
        }

        // ---- 32-CTA group barrier (skip after final step) ----
        if (t + 1 < Sq) {
            __threadfence();        // release: h writes visible before arrive
            __syncthreads();        // all threads done epilogue (zs reads too)
            if (tid == 0) {
                atomicAdd(&g_barrier[gid], 1u);
                unsigned tgt = 32u * (unsigned)(t + 1);
                while (*((volatile unsigned*)&g_barrier[gid]) < tgt) {}
                __threadfence();    // acquire
            }
            __syncthreads();
        }
    }
}

// ---------------------------------------------------------------------------
// Output GEMM via HMMA split-bf16:
//   out[m][n] = Ahi*Bhi + Ahi*Blo + Alo*Bhi + bd[n]
// launch_bounds(256,2): regs capped at 128 so 2 CTAs co-reside (160KB smem).
// ---------------------------------------------------------------------------
#define OG_BK       32
#define OG_CHUNKS   (Kout / OG_BK)      // 64
#define OG_RSTRIDE  80
#define OG_TILE_B   (128 * OG_RSTRIDE)  // 10240
#define OG_STAGE_B  (4 * OG_TILE_B)
#define OG_SMEM     (2 * OG_STAGE_B)    // 81920

__global__ __launch_bounds__(256, 2) void out_gemm_kernel(
    const __nv_bfloat16* __restrict__ Ahi, const __nv_bfloat16* __restrict__ Alo,
    const __nv_bfloat16* __restrict__ Bhi, const __nv_bfloat16* __restrict__ Blo,
    const float* __restrict__ bd, float* __restrict__ out)
{
    extern __shared__ char smem[];
    const unsigned sb = smem_to_u32(smem);
    const int tid = threadIdx.x;
    const int wid = tid >> 5;
    const int lane = tid & 31;
    const int warp_m = wid >> 2;
    const int warp_n = wid & 3;
    const int n0 = blockIdx.x * 128;
    const int m0 = blockIdx.y * 128;

    const __nv_bfloat16* srcs[4] = {Ahi, Alo, Bhi, Blo};
    const int rowbase[4] = {m0, m0, n0, n0};

    auto issue_chunk = [&](int kc, int buf) {
        const unsigned bb = sb + buf * OG_STAGE_B;
#pragma unroll
        for (int i = 0; i < 8; i++) {
            int id   = i * 256 + tid;
            int tile = id >> 9;
            int rem  = id & 511;
            int r    = rem >> 2;
            int ch   = rem & 3;
            unsigned dst = bb + tile * OG_TILE_B + r * OG_RSTRIDE + ch * 16;
            const void* g = srcs[tile] +
                            (size_t)(rowbase[tile] + r) * Kout + kc + ch * 8;
            cp_async16(dst, g);
        }
        CP_COMMIT();
    };

    float acc[4][4][4];
#pragma unroll
    for (int mt = 0; mt < 4; mt++)
#pragma unroll
        for (int nt = 0; nt < 4; nt++)
#pragma unroll
            for (int q = 0; q < 4; q++) acc[mt][nt][q] = 0.f;

    issue_chunk(0, 0);
    issue_chunk(OG_BK, 1);

    for (int c = 0; c < OG_CHUNKS; c++) {
        if (c < OG_CHUNKS - 1) { CP_WAIT(1); } else { CP_WAIT(0); }
        __syncthreads();

        const unsigned bb  = sb + (c & 1) * OG_STAGE_B;
        const unsigned sAh = bb;
        const unsigned sAl = bb + OG_TILE_B;
        const unsigned sBh = bb + 2 * OG_TILE_B;
        const unsigned sBl = bb + 3 * OG_TILE_B;

#pragma unroll
        for (int kh = 0; kh < 2; kh++) {
            const int koff = kh * 32;
            const unsigned a_off =
                (warp_m * 64 + (lane & 15)) * OG_RSTRIDE + koff + ((lane >> 4) << 4);
            const unsigned b_off =
                (warp_n * 32 + (lane & 7) + ((lane >> 4) << 3)) * OG_RSTRIDE +
                koff + (((lane >> 3) & 1) << 4);

            unsigned aH[4][4], aL[4][4], bH[4][2], bL[4][2];
#pragma unroll
            for (int mt = 0; mt < 4; mt++) {
                ldmatrix_x4(aH[mt], sAh + a_off + mt * 16 * OG_RSTRIDE);
                ldmatrix_x4(aL[mt], sAl + a_off + mt * 16 * OG_RSTRIDE);
            }
#pragma unroll
            for (int np = 0; np < 2; np++) {
                unsigned r4[4];
                ldmatrix_x4(r4, sBh + b_off + np * 16 * OG_RSTRIDE);
                bH[np * 2][0] = r4[0]; bH[np * 2][1] = r4[1];
                bH[np * 2 + 1][0] = r4[2]; bH[np * 2 + 1][1] = r4[3];
                ldmatrix_x4(r4, sBl + b_off + np * 16 * OG_RSTRIDE);
                bL[np * 2][0] = r4[0]; bL[np * 2][1] = r4[1];
                bL[np * 2 + 1][0] = r4[2]; bL[np * 2 + 1][1] = r4[3];
            }

#pragma unroll
            for (int mt = 0; mt < 4; mt++)
#pragma unroll
                for (int nt = 0; nt < 4; nt++) {
                    mma_bf16(acc[mt][nt], aH[mt], bH[nt]);
                    mma_bf16(acc[mt][nt], aH[mt], bL[nt]);
                    mma_bf16(acc[mt][nt], aL[mt], bH[nt]);
                }
        }

        __syncthreads();
        if (c + 2 < OG_CHUNKS) issue_chunk((c + 2) * OG_BK, c & 1);
    }

#pragma unroll
    for (int mt = 0; mt < 4; mt++) {
        int r0 = m0 + warp_m * 64 + mt * 16 + (lane >> 2);
#pragma unroll
        for (int nt = 0; nt < 4; nt++) {
            int col = n0 + warp_n * 32 + nt * 8 + 2 * (lane & 3);
            float b0v = bd[col], b1v = bd[col + 1];
            float2 v0 = make_float2(acc[mt][nt][0] + b0v, acc[mt][nt][1] + b1v);
            float2 v1 = make_float2(acc[mt][nt][2] + b0v, acc[mt][nt][3] + b1v);
            *reinterpret_cast<float2*>(out + (size_t)r0 * Vq + col) = v0;
            *reinterpret_cast<float2*>(out + (size_t)(r0 + 8) * Vq + col) = v1;
        }
    }
}

// ---------------------------------------------------------------------------
// Launch
// ---------------------------------------------------------------------------
extern "C" void kernel_launch(void* const* d_in, const int* in_sizes, int n_in,
                              void* d_out, int out_size) {
    (void)in_sizes; (void)n_in; (void)out_size;
    const int*   tokens = (const int*)  d_in[0];
    const float* emb    = (const float*)d_in[1];
    const float* Wf     = (const float*)d_in[2];
    const float* Uf     = (const float*)d_in[3];
    const float* bf     = (const float*)d_in[4];
    const float* Wb     = (const float*)d_in[5];
    const float* Ub     = (const float*)d_in[6];
    const float* bb     = (const float*)d_in[7];
    const float* Wd     = (const float*)d_in[8];
    const float* bd     = (const float*)d_in[9];
    float* out = (float*)d_out;

    float *p_Wtf, *p_Wtb, *p_btf, *p_btb, *p_embWtf, *p_embWtb;
    __nv_bfloat16 *p_Ahi, *p_Alo, *p_Bhi, *p_Blo;
    cudaGetSymbolAddress((void**)&p_Wtf,    g_Wtf);
    cudaGetSymbolAddress((void**)&p_Wtb,    g_Wtb);
    cudaGetSymbolAddress((void**)&p_btf,    g_btf);
    cudaGetSymbolAddress((void**)&p_btb,    g_btb);
    cudaGetSymbolAddress((void**)&p_embWtf, g_embWtf);
    cudaGetSymbolAddress((void**)&p_embWtb, g_embWtb);
    cudaGetSymbolAddress((void**)&p_Ahi,    g_Ahi);
    cudaGetSymbolAddress((void**)&p_Alo,    g_Alo);
    cudaGetSymbolAddress((void**)&p_Bhi,    g_Bhi);
    cudaGetSymbolAddress((void**)&p_Blo,    g_Blo);

    cudaFuncSetAttribute(out_gemm_kernel,
                         cudaFuncAttributeMaxDynamicSharedMemorySize, OG_SMEM);
    cudaFuncSetAttribute(lstm_persistent_kernel,
                         cudaFuncAttributeMaxDynamicSharedMemorySize, LS_SMEM);

    init_state_kernel<<<(Bq * Hq + 255) / 256, 256>>>();
    interleave_W_kernel<<<(Eq * G4H + 255) / 256, 256>>>(Wf, Wb, bf, bb);
    split_transpose_U_kernel<<<dim3(Hq / 32, Hq / 32, 8), dim3(32, 8)>>>(Uf, Ub);
    split_transpose_Wd_kernel<<<dim3(Vq / 32, Kout / 32), dim3(32, 8)>>>(Wd);

    // embWt = emb @ Wt + bt  (gate-interleaved, bias folded)
    gemm_bias_kernel<<<dim3(G4H / 128, Vq / 128), 256>>>(
        emb, p_Wtf, p_btf, p_embWtf, Vq, G4H, Eq);
    gemm_bias_kernel<<<dim3(G4H / 128, Vq / 128), 256>>>(
        emb, p_Wtb, p_btb, p_embWtb, Vq, G4H, Eq);

    // ALL 256 recurrent steps in one persistent launch
    lstm_persistent_kernel<<<dim3(G4H / 128, Bq / 64, 2), 512, LS_SMEM>>>(tokens);

    out_gemm_kernel<<<dim3(Vq / 128, Mout / 128), 256, OG_SMEM>>>(
        p_Ahi, p_Alo, p_Bhi, p_Blo, bd, out);
}

// round 11
// speedup vs baseline: 1.5039x; 1.5039x over previous
#include <cuda_runtime.h>
#include <cuda_fp16.h>
#include <math.h>

// Problem dims
#define Bq   128
#define Sq   256
#define Eq   512
#define Hq   1024
#define Vq   2048
#define G4H  4096   // 4*H
#define Kout 2048   // 2*H (output GEMM K)
#define Mout (Bq * Sq)

// ---------------------------------------------------------------------------
// Scratch (device globals; no allocation allowed)
// ---------------------------------------------------------------------------
__device__ float g_Wtf[Eq * G4H];            //  8 MB: Wf gate-interleaved
__device__ float g_Wtb[Eq * G4H];
__device__ float g_btf[G4H];
__device__ float g_btb[G4H];
__device__ float g_embWtf[Vq * G4H];         // 32 MB (bias folded)
__device__ float g_embWtb[Vq * G4H];
__device__ float g_c[2][Bq * Hq];            // [dir] cell state (fp32)
// Recurrent weights, plain fp16, gate-interleaved, TRANSPOSED: [n=j*4+g][k]
__device__ __half g_Uhif[G4H * Hq];          // 8 MB
__device__ __half g_Uhib[G4H * Hq];
// hcat as split-fp16; row m = b*S+s, col = dir*H+j. A operand of the next
// recurrent step (rows at s_prev) and of the output GEMM.
__device__ __half g_Ahi[(size_t)Mout * Kout]; // 128 MB
__device__ __half g_Alo[(size_t)Mout * Kout]; // 128 MB
// Wd transposed, plain fp16: B[n][k] = Wd[k][n]
__device__ __half g_Bhi[Vq * Kout];          // 8 MB

// ---------------------------------------------------------------------------
// f32x2 packed-FMA helpers (embW precompute GEMM)
// ---------------------------------------------------------------------------
__device__ __forceinline__ unsigned long long dup2(float x) {
    unsigned long long r;
    asm("mov.b64 %0, {%1, %1};" : "=l"(r) : "f"(x));
    return r;
}
__device__ __forceinline__ void ffma2(unsigned long long &acc,
                                      unsigned long long a,
                                      unsigned long long b) {
    asm("fma.rn.f32x2 %0, %1, %2, %0;" : "+l"(acc) : "l"(a), "l"(b));
}
__device__ __forceinline__ float2 unpack2(unsigned long long v) {
    float2 f;
    asm("mov.b64 {%0, %1}, %2;" : "=f"(f.x), "=f"(f.y) : "l"(v));
    return f;
}
__device__ __forceinline__ float sigmoidf_fast(float x) {
    return __fdividef(1.f, 1.f + __expf(-x));
}
__device__ __forceinline__ unsigned smem_to_u32(const void* p) {
    unsigned a;
    asm("{ .reg .u64 t; cvta.to.shared.u64 t, %1; cvt.u32.u64 %0, t; }"
        : "=r"(a) : "l"(p));
    return a;
}

// ---------------------------------------------------------------------------
// sm_80+ portable async-copy + ldmatrix + HMMA (fp16, fp32 accumulate)
// ---------------------------------------------------------------------------
__device__ __forceinline__ void cp_async16(unsigned smem_addr, const void* gptr) {
    asm volatile("cp.async.cg.shared.global [%0], [%1], 16;"
                 :: "r"(smem_addr), "l"(gptr));
}
#define CP_COMMIT() asm volatile("cp.async.commit_group;" ::: "memory")
#define CP_WAIT(n)  asm volatile("cp.async.wait_group %0;" :: "n"(n) : "memory")

__device__ __forceinline__ void ldmatrix_x4(unsigned* r, unsigned addr) {
    asm volatile("ldmatrix.sync.aligned.m8n8.x4.shared.b16 {%0,%1,%2,%3}, [%4];"
                 : "=r"(r[0]), "=r"(r[1]), "=r"(r[2]), "=r"(r[3]) : "r"(addr));
}
__device__ __forceinline__ void mma_f16(float* c, const unsigned* a,
                                        const unsigned* b) {
    asm volatile(
        "mma.sync.aligned.m16n8k16.row.col.f32.f16.f16.f32 "
        "{%0,%1,%2,%3}, {%4,%5,%6,%7}, {%8,%9}, {%0,%1,%2,%3};"
        : "+f"(c[0]), "+f"(c[1]), "+f"(c[2]), "+f"(c[3])
        : "r"(a[0]), "r"(a[1]), "r"(a[2]), "r"(a[3]), "r"(b[0]), "r"(b[1]));
}

// ---------------------------------------------------------------------------
// Zero the cell state
// ---------------------------------------------------------------------------
__global__ void init_state_kernel() {
    int i = blockIdx.x * blockDim.x + threadIdx.x;
    if (i < Bq * Hq) { g_c[0][i] = 0.f; g_c[1][i] = 0.f; }
}

// ---------------------------------------------------------------------------
// Gate-interleave W, b:  Wt[e][j*4+g] = W[e][g*H+j]
// ---------------------------------------------------------------------------
__global__ void interleave_W_kernel(const float* __restrict__ Wf,
                                    const float* __restrict__ Wb,
                                    const float* __restrict__ bf,
                                    const float* __restrict__ bb) {
    int idx = blockIdx.x * blockDim.x + threadIdx.x;
    if (idx < Eq * G4H) {
        int e = idx >> 12;
        int c = idx & 4095;
        int src = e * G4H + (c & 3) * Hq + (c >> 2);
        g_Wtf[idx] = Wf[src];
        g_Wtb[idx] = Wb[src];
    }
    if (idx < G4H) {
        int src = (idx & 3) * Hq + (idx >> 2);
        g_btf[idx] = bf[src];
        g_btb[idx] = bb[src];
    }
}

// ---------------------------------------------------------------------------
// fp16 + transpose + gate-interleave U:  U16[dir][(j*4+g)][k] = fp16(U[k][g*H+j])
// ---------------------------------------------------------------------------
__global__ void split_transpose_U_kernel(const float* __restrict__ Uf,
                                         const float* __restrict__ Ub) {
    __shared__ float ts[32][33];
    int j0 = blockIdx.x * 32;
    int k0 = blockIdx.y * 32;
    int g   = blockIdx.z & 3;
    int dir = blockIdx.z >> 2;
    const float* U = dir ? Ub : Uf;
    __half* Dhi = dir ? g_Uhib : g_Uhif;
    int tx = threadIdx.x, ty = threadIdx.y;
#pragma unroll
    for (int i = 0; i < 32; i += 8)
        ts[ty + i][tx] = U[(size_t)(k0 + ty + i) * G4H + g * Hq + j0 + tx];
    __syncthreads();
#pragma unroll
    for (int i = 0; i < 32; i += 8) {
        int j = j0 + ty + i;
        float v = ts[tx][ty + i];          // U[k0+tx][g*H + j]
        size_t o = (size_t)((j << 2) + g) * Hq + k0 + tx;
        Dhi[o] = __float2half(v);
    }
}

// ---------------------------------------------------------------------------
// fp16 + transpose Wd:  Bhi[n][k] = fp16(Wd[k][n])
// ---------------------------------------------------------------------------
__global__ void split_transpose_Wd_kernel(const float* __restrict__ Wd) {
    __shared__ float ts[32][33];
    int n0 = blockIdx.x * 32;
    int k0 = blockIdx.y * 32;
    int tx = threadIdx.x, ty = threadIdx.y;
#pragma unroll
    for (int i = 0; i < 32; i += 8)
        ts[ty + i][tx] = Wd[(size_t)(k0 + ty + i) * Vq + n0 + tx];
    __syncthreads();
#pragma unroll
    for (int i = 0; i < 32; i += 8) {
        float v = ts[tx][ty + i];            // Wd[k0+tx][n0+ty+i]
        size_t o = (size_t)(n0 + ty + i) * Kout + k0 + tx;
        g_Bhi[o] = __float2half(v);
    }
}

// ---------------------------------------------------------------------------
// Generic tiled fp32 GEMM (embW precompute):  C = A @ B + bias
// ---------------------------------------------------------------------------
__global__ __launch_bounds__(256) void gemm_bias_kernel(
    const float* __restrict__ A, const float* __restrict__ B,
    const float* __restrict__ bias, float* __restrict__ C,
    int M, int N, int K)
{
    __shared__ float As[16][128];
    __shared__ float Bs[16][128];

    const int tid = threadIdx.x;
    const int n0  = blockIdx.x * 128;
    const int m0  = blockIdx.y * 128;

    const int a_kq = tid & 3;
    const int a_r  = tid >> 2;
    const int b_c4 = tid & 31;
    const int b_k  = tid >> 5;

    const int trow = tid >> 4;
    const int tcol = tid & 15;

    unsigned long long acc[4][8];
#pragma unroll
    for (int i = 0; i < 4; i++)
#pragma unroll
        for (int j = 0; j < 8; j++) acc[i][j] = 0ull;

    float4 pa0, pa1, pb0, pb1;
    pa0 = *reinterpret_cast<const float4*>(&A[(m0 + a_r)      * K + a_kq * 4]);
    pa1 = *reinterpret_cast<const float4*>(&A[(m0 + a_r + 64) * K + a_kq * 4]);
    pb0 = *reinterpret_cast<const float4*>(&B[(b_k)     * N + n0 + b_c4 * 4]);
    pb1 = *reinterpret_cast<const float4*>(&B[(b_k + 8) * N + n0 + b_c4 * 4]);

    for (int kc = 0; kc < K; kc += 16) {
        As[a_kq * 4 + 0][a_r] = pa0.x;
        As[a_kq * 4 + 1][a_r] = pa0.y;
        As[a_kq * 4 + 2][a_r] = pa0.z;
        As[a_kq * 4 + 3][a_r] = pa0.w;
        As[a_kq * 4 + 0][a_r + 64] = pa1.x;
        As[a_kq * 4 + 1][a_r + 64] = pa1.y;
        As[a_kq * 4 + 2][a_r + 64] = pa1.z;
        As[a_kq * 4 + 3][a_r + 64] = pa1.w;
        *reinterpret_cast<float4*>(&Bs[b_k][b_c4 * 4])     = pb0;
        *reinterpret_cast<float4*>(&Bs[b_k + 8][b_c4 * 4]) = pb1;
        __syncthreads();

        const int kn = kc + 16;
        if (kn < K) {
            pa0 = *reinterpret_cast<const float4*>(&A[(m0 + a_r)      * K + kn + a_kq * 4]);
            pa1 = *reinterpret_cast<const float4*>(&A[(m0 + a_r + 64) * K + kn + a_kq * 4]);
            pb0 = *reinterpret_cast<const float4*>(&B[(kn + b_k)     * N + n0 + b_c4 * 4]);
            pb1 = *reinterpret_cast<const float4*>(&B[(kn + b_k + 8) * N + n0 + b_c4 * 4]);
        }

#pragma unroll
        for (int k = 0; k < 16; k++) {
            const ulonglong2* ap =
                reinterpret_cast<const ulonglong2*>(&As[k][trow * 8]);
            ulonglong2 av0 = ap[0];
            ulonglong2 av1 = ap[1];
            unsigned long long a4[4] = {av0.x, av0.y, av1.x, av1.y};

            float4 bv0 = *reinterpret_cast<const float4*>(&Bs[k][tcol * 8]);
            float4 bv1 = *reinterpret_cast<const float4*>(&Bs[k][tcol * 8 + 4]);
            unsigned long long bd[8];
            bd[0] = dup2(bv0.x); bd[1] = dup2(bv0.y);
            bd[2] = dup2(bv0.z); bd[3] = dup2(bv0.w);
            bd[4] = dup2(bv1.x); bd[5] = dup2(bv1.y);
            bd[6] = dup2(bv1.z); bd[7] = dup2(bv1.w);

#pragma unroll
            for (int ip = 0; ip < 4; ip++)
#pragma unroll
                for (int j = 0; j < 8; j++)
                    ffma2(acc[ip][j], a4[ip], bd[j]);
        }
        __syncthreads();
    }

    float bsv[8];
#pragma unroll
    for (int j = 0; j < 8; j++) bsv[j] = bias[n0 + tcol * 8 + j];

#pragma unroll
    for (int ip = 0; ip < 4; ip++) {
        float2 v[8];
#pragma unroll
        for (int j = 0; j < 8; j++) v[j] = unpack2(acc[ip][j]);
        int r0 = m0 + trow * 8 + ip * 2;
        float* c0 = C + (size_t)r0 * N + n0 + tcol * 8;
        float* c1 = c0 + N;
        float4 x0 = make_float4(v[0].x + bsv[0], v[1].x + bsv[1],
                                v[2].x + bsv[2], v[3].x + bsv[3]);
        float4 x1 = make_float4(v[4].x + bsv[4], v[5].x + bsv[5],
                                v[6].x + bsv[6], v[7].x + bsv[7]);
        float4 y0 = make_float4(v[0].y + bsv[0], v[1].y + bsv[1],
                                v[2].y + bsv[2], v[3].y + bsv[3]);
        float4 y1 = make_float4(v[4].y + bsv[4], v[5].y + bsv[5],
                                v[6].y + bsv[6], v[7].y + bsv[7]);
        *reinterpret_cast<float4*>(c0)     = x0;
        *reinterpret_cast<float4*>(c0 + 4) = x1;
        *reinterpret_cast<float4*>(c1)     = y0;
        *reinterpret_cast<float4*>(c1 + 4) = y1;
    }
}

// ---------------------------------------------------------------------------
// One LSTM step via HMMA fp16, 2-pass split-A:  z = (Ahi + Alo) @ U16^T
// 512 threads (16 warps, 4m x 4n). CTA tile 64 batch x 128 interleaved cols.
// Grid (G4H/128=32, Bq/64=2, dir=2) = 128 CTAs.
// ---------------------------------------------------------------------------
#define LS_RS     80                       // bytes per 32-fp16 SMEM row
#define LS_ATILE  (64 * LS_RS)             // 5120
#define LS_BTILE  (128 * LS_RS)            // 10240
#define LS_STAGE  (2 * LS_ATILE + LS_BTILE)  // 20480
#define LS_SMEM   (2 * LS_STAGE)           // 40960 (z-tile aliases this)

__global__ __launch_bounds__(512, 1) void lstm_mma_step_kernel(
    const int* __restrict__ tokens, int t)
{
    extern __shared__ char smem[];
    const unsigned sb = smem_to_u32(smem);
    float (*zs)[132] = reinterpret_cast<float (*)[132]>(smem);  // 64x132 fp32
    __shared__ int toks[64];

    const int tid = threadIdx.x;
    const int wid = tid >> 5;
    const int lane = tid & 31;
    const int warp_m = wid >> 2;        // 0..3 (16 rows each)
    const int warp_n = wid & 3;         // 0..3 (32 cols each)
    const int c0  = blockIdx.x * 128;   // interleaved col base
    const int b0  = blockIdx.y * 64;
    const int dir = blockIdx.z;
    const int s  = dir ? (Sq - 1 - t) : t;
    const int sp = dir ? (Sq - t) : (t - 1);   // previous step's s (t>0)

    const __half* Uhi = dir ? g_Uhib : g_Uhif;

    if (tid < 64) toks[tid] = tokens[(b0 + tid) * Sq + s];

    float acc[4][4];                    // [nt][quad]
#pragma unroll
    for (int nt = 0; nt < 4; nt++)
#pragma unroll
        for (int q = 0; q < 4; q++) acc[nt][q] = 0.f;

    if (t > 0) {
        auto issue_chunk = [&](int kc, int buf) {
            const unsigned bb = sb + buf * LS_STAGE;
#pragma unroll
            for (int i = 0; i < 2; i++) {
                int id = i * 512 + tid;            // 0..1023
                if (id < 512) {
                    int part = id >> 8;            // 0 = Ahi, 1 = Alo
                    int rem = id & 255;
                    int r = rem >> 2, ch = rem & 3;
                    const __half* src = part ? g_Alo : g_Ahi;
                    unsigned dst = bb + part * LS_ATILE + r * LS_RS + ch * 16;
                    cp_async16(dst, src +
                        ((size_t)(b0 + r) * Sq + sp) * Kout + dir * Hq + kc + ch * 8);
                } else {
                    int id2 = id - 512;            // 0..511 (Uhi)
                    int r = id2 >> 2, ch = id2 & 3;
                    unsigned dst = bb + 2 * LS_ATILE + r * LS_RS + ch * 16;
                    cp_async16(dst, Uhi + (size_t)(c0 + r) * Hq + kc + ch * 8);
                }
            }
            CP_COMMIT();
        };

        issue_chunk(0, 0);
        issue_chunk(32, 1);

        for (int c = 0; c < 32; c++) {
            if (c < 31) { CP_WAIT(1); } else { CP_WAIT(0); }
            __syncthreads();

            const unsigned bb  = sb + (c & 1) * LS_STAGE;
            const unsigned sAh = bb;
            const unsigned sAl = bb + LS_ATILE;
            const unsigned sBh = bb + 2 * LS_ATILE;

#pragma unroll
            for (int kh = 0; kh < 2; kh++) {
                const int koff = kh * 32;          // bytes (16 fp16)
                const unsigned a_off =
                    (warp_m * 16 + (lane & 15)) * LS_RS + koff + ((lane >> 4) << 4);
                const unsigned b_off =
                    (warp_n * 32 + (lane & 7) + ((lane >> 4) << 3)) * LS_RS +
                    koff + (((lane >> 3) & 1) << 4);

                unsigned aH[4], aL[4], bH[4][2];
                ldmatrix_x4(aH, sAh + a_off);
                ldmatrix_x4(aL, sAl + a_off);
#pragma unroll
                for (int np = 0; np < 2; np++) {
                    unsigned r4[4];
                    ldmatrix_x4(r4, sBh + b_off + np * 16 * LS_RS);
                    bH[np * 2][0] = r4[0]; bH[np * 2][1] = r4[1];
                    bH[np * 2 + 1][0] = r4[2]; bH[np * 2 + 1][1] = r4[3];
                }

#pragma unroll
                for (int nt = 0; nt < 4; nt++) {
                    mma_f16(acc[nt], aH, bH[nt]);
                    mma_f16(acc[nt], aL, bH[nt]);
                }
            }

            __syncthreads();
            if (c + 2 < 32) issue_chunk((c + 2) * 32, c & 1);
        }
    }

    __syncthreads();   // all MMA reads done; safe to alias stage smem as zs

    // fragments -> z tile
    {
        int r = warp_m * 16 + (lane >> 2);
#pragma unroll
        for (int nt = 0; nt < 4; nt++) {
            int col = warp_n * 32 + nt * 8 + 2 * (lane & 3);
            *reinterpret_cast<float2*>(&zs[r][col]) =
                make_float2(acc[nt][0], acc[nt][1]);
            *reinterpret_cast<float2*>(&zs[r + 8][col]) =
                make_float2(acc[nt][2], acc[nt][3]);
        }
    }
    __syncthreads();

    // fused gate update: 64 rows x 32 hidden units = 2048 items / 512 threads
    const float* embW = dir ? g_embWtb : g_embWtf;
    float* cptr = &g_c[dir][0];
    const int j0q = c0 >> 2;

#pragma unroll
    for (int it = 0; it < 4; it++) {
        int idx = it * 512 + tid;
        int r  = idx >> 5;     // 0..63
        int jj = idx & 31;     // 0..31
        int j = j0q + jj;

        float4 z4 = *reinterpret_cast<const float4*>(&zs[r][jj * 4]);
        int tok = toks[r];
        float4 ew = *reinterpret_cast<const float4*>(
            &embW[(size_t)tok * G4H + (j << 2)]);
        float zi = z4.x + ew.x;
        float zf = z4.y + ew.y;
        float zg = z4.z + ew.z;
        float zo = z4.w + ew.w;

        float ig = sigmoidf_fast(zi);
        float fg = sigmoidf_fast(zf);
        float og = sigmoidf_fast(zo);
        float gg = dir ? fmaxf(zg, 0.f) : tanhf(zg);

        int ci = (b0 + r) * Hq + j;
        float cv = fg * cptr[ci] + ig * gg;
        cptr[ci] = cv;
        float hc = dir ? fmaxf(cv, 0.f) : tanhf(cv);
        float hv = og * hc;

        size_t ao = ((size_t)(b0 + r) * Sq + s) * Kout + dir * Hq + j;
        __half hi = __float2half(hv);
        g_Ahi[ao] = hi;
        g_Alo[ao] = __float2half(hv - __half2float(hi));
    }
}

// ---------------------------------------------------------------------------
// Output GEMM via HMMA fp16, 2-pass split-A:
//   out[m][n] = (Ahi + Alo) @ Bhi^T + bd[n]
// launch_bounds(256,2): 2 CTAs co-reside (2 x 61.4KB smem).
// ---------------------------------------------------------------------------
#define OG_BK       32
#define OG_CHUNKS   (Kout / OG_BK)      // 64
#define OG_RSTRIDE  80
#define OG_TILE_B   (128 * OG_RSTRIDE)  // 10240
#define OG_STAGE_B  (3 * OG_TILE_B)     // Ahi, Alo, Bhi
#define OG_SMEM     (2 * OG_STAGE_B)    // 61440

__global__ __launch_bounds__(256, 2) void out_gemm_kernel(
    const __half* __restrict__ Ahi, const __half* __restrict__ Alo,
    const __half* __restrict__ Bhi,
    const float* __restrict__ bd, float* __restrict__ out)
{
    extern __shared__ char smem[];
    const unsigned sb = smem_to_u32(smem);
    const int tid = threadIdx.x;
    const int wid = tid >> 5;
    const int lane = tid & 31;
    const int warp_m = wid >> 2;
    const int warp_n = wid & 3;
    const int n0 = blockIdx.x * 128;
    const int m0 = blockIdx.y * 128;

    const __half* srcs[3] = {Ahi, Alo, Bhi};
    const int rowbase[3] = {m0, m0, n0};

    auto issue_chunk = [&](int kc, int buf) {
        const unsigned bb = sb + buf * OG_STAGE_B;
#pragma unroll
        for (int i = 0; i < 6; i++) {
            int id   = i * 256 + tid;    // 0..1535
            int tile = id >> 9;          // 0..2
            int rem  = id & 511;
            int r    = rem >> 2;
            int ch   = rem & 3;
            unsigned dst = bb + tile * OG_TILE_B + r * OG_RSTRIDE + ch * 16;
            const void* g = srcs[tile] +
                            (size_t)(rowbase[tile] + r) * Kout + kc + ch * 8;
            cp_async16(dst, g);
        }
        CP_COMMIT();
    };

    float acc[4][4][4];
#pragma unroll
    for (int mt = 0; mt < 4; mt++)
#pragma unroll
        for (int nt = 0; nt < 4; nt++)
#pragma unroll
            for (int q = 0; q < 4; q++) acc[mt][nt][q] = 0.f;

    issue_chunk(0, 0);
    issue_chunk(OG_BK, 1);

    for (int c = 0; c < OG_CHUNKS; c++) {
        if (c < OG_CHUNKS - 1) { CP_WAIT(1); } else { CP_WAIT(0); }
        __syncthreads();

        const unsigned bb  = sb + (c & 1) * OG_STAGE_B;
        const unsigned sAh = bb;
        const unsigned sAl = bb + OG_TILE_B;
        const unsigned sBh = bb + 2 * OG_TILE_B;

#pragma unroll
        for (int kh = 0; kh < 2; kh++) {
            const int koff = kh * 32;
            const unsigned a_off =
                (warp_m * 64 + (lane & 15)) * OG_RSTRIDE + koff + ((lane >> 4) << 4);
            const unsigned b_off =
                (warp_n * 32 + (lane & 7) + ((lane >> 4) << 3)) * OG_RSTRIDE +
                koff + (((lane >> 3) & 1) << 4);

            unsigned aH[4][4], aL[4][4], bH[4][2];
#pragma unroll
            for (int mt = 0; mt < 4; mt++) {
                ldmatrix_x4(aH[mt], sAh + a_off + mt * 16 * OG_RSTRIDE);
                ldmatrix_x4(aL[mt], sAl + a_off + mt * 16 * OG_RSTRIDE);
            }
#pragma unroll
            for (int np = 0; np < 2; np++) {
                unsigned r4[4];
                ldmatrix_x4(r4, sBh + b_off + np * 16 * OG_RSTRIDE);
                bH[np * 2][0] = r4[0]; bH[np * 2][1] = r4[1];
                bH[np * 2 + 1][0] = r4[2]; bH[np * 2 + 1][1] = r4[3];
            }

#pragma unroll
            for (int mt = 0; mt < 4; mt++)
#pragma unroll
                for (int nt = 0; nt < 4; nt++) {
                    mma_f16(acc[mt][nt], aH[mt], bH[nt]);
                    mma_f16(acc[mt][nt], aL[mt], bH[nt]);
                }
        }

        __syncthreads();
        if (c + 2 < OG_CHUNKS) issue_chunk((c + 2) * OG_BK, c & 1);
    }

#pragma unroll
    for (int mt = 0; mt < 4; mt++) {
        int r0 = m0 + warp_m * 64 + mt * 16 + (lane >> 2);
#pragma unroll
        for (int nt = 0; nt < 4; nt++) {
            int col = n0 + warp_n * 32 + nt * 8 + 2 * (lane & 3);
            float b0v = bd[col], b1v = bd[col + 1];
            float2 v0 = make_float2(acc[mt][nt][0] + b0v, acc[mt][nt][1] + b1v);
            float2 v1 = make_float2(acc[mt][nt][2] + b0v, acc[mt][nt][3] + b1v);
            *reinterpret_cast<float2*>(out + (size_t)r0 * Vq + col) = v0;
            *reinterpret_cast<float2*>(out + (size_t)(r0 + 8) * Vq + col) = v1;
        }
    }
}

// ---------------------------------------------------------------------------
// Launch
// ---------------------------------------------------------------------------
extern "C" void kernel_launch(void* const* d_in, const int* in_sizes, int n_in,
                              void* d_out, int out_size) {
    (void)in_sizes; (void)n_in; (void)out_size;
    const int*   tokens = (const int*)  d_in[0];
    const float* emb    = (const float*)d_in[1];
    const float* Wf     = (const float*)d_in[2];
    const float* Uf     = (const float*)d_in[3];
    const float* bf     = (const float*)d_in[4];
    const float* Wb     = (const float*)d_in[5];
    const float* Ub     = (const float*)d_in[6];
    const float* bb     = (const float*)d_in[7];
    const float* Wd     = (const float*)d_in[8];
    const float* bd     = (const float*)d_in[9];
    float* out = (float*)d_out;

    float *p_Wtf, *p_Wtb, *p_btf, *p_btb, *p_embWtf, *p_embWtb;
    __half *p_Ahi, *p_Alo, *p_Bhi;
    cudaGetSymbolAddress((void**)&p_Wtf,    g_Wtf);
    cudaGetSymbolAddress((void**)&p_Wtb,    g_Wtb);
    cudaGetSymbolAddress((void**)&p_btf,    g_btf);
    cudaGetSymbolAddress((void**)&p_btb,    g_btb);
    cudaGetSymbolAddress((void**)&p_embWtf, g_embWtf);
    cudaGetSymbolAddress((void**)&p_embWtb, g_embWtb);
    cudaGetSymbolAddress((void**)&p_Ahi,    g_Ahi);
    cudaGetSymbolAddress((void**)&p_Alo,    g_Alo);
    cudaGetSymbolAddress((void**)&p_Bhi,    g_Bhi);

    cudaFuncSetAttribute(out_gemm_kernel,
                         cudaFuncAttributeMaxDynamicSharedMemorySize, OG_SMEM);
    cudaFuncSetAttribute(lstm_mma_step_kernel,
                         cudaFuncAttributeMaxDynamicSharedMemorySize, LS_SMEM);

    init_state_kernel<<<(Bq * Hq + 255) / 256, 256>>>();
    interleave_W_kernel<<<(Eq * G4H + 255) / 256, 256>>>(Wf, Wb, bf, bb);
    split_transpose_U_kernel<<<dim3(Hq / 32, Hq / 32, 8), dim3(32, 8)>>>(Uf, Ub);
    split_transpose_Wd_kernel<<<dim3(Vq / 32, Kout / 32), dim3(32, 8)>>>(Wd);

    // embWt = emb @ Wt + bt  (gate-interleaved, bias folded)
    gemm_bias_kernel<<<dim3(G4H / 128, Vq / 128), 256>>>(
        emb, p_Wtf, p_btf, p_embWtf, Vq, G4H, Eq);
    gemm_bias_kernel<<<dim3(G4H / 128, Vq / 128), 256>>>(
        emb, p_Wtb, p_btb, p_embWtb, Vq, G4H, Eq);

    // 256 sequential recurrent steps (both directions per launch), HMMA fp16
    for (int t = 0; t < Sq; t++) {
        lstm_mma_step_kernel<<<dim3(G4H / 128, Bq / 64, 2), 512, LS_SMEM>>>(
            tokens, t);
    }

    out_gemm_kernel<<<dim3(Vq / 128, Mout / 128), 256, OG_SMEM>>>(
        p_Ahi, p_Alo, p_Bhi, bd, out);
}

// round 12
// speedup vs baseline: 1.8929x; 1.2586x over previous
#include <cuda_runtime.h>
#include <cuda_fp16.h>
#include <math.h>

// Problem dims
#define Bq   128
#define Sq   256
#define Eq   512
#define Hq   1024
#define Vq   2048
#define G4H  4096   // 4*H
#define Kout 2048   // 2*H (output GEMM K)
#define Mout (Bq * Sq)

// ---------------------------------------------------------------------------
// Scratch (device globals; no allocation allowed)
// ---------------------------------------------------------------------------
__device__ float g_Wtf[Eq * G4H];            //  8 MB: Wf gate-interleaved
__device__ float g_Wtb[Eq * G4H];
__device__ float g_btf[G4H];
__device__ float g_btb[G4H];
__device__ float g_embWtf[Vq * G4H];         // 32 MB (bias folded)
__device__ float g_embWtb[Vq * G4H];
__device__ float g_c[2][Bq * Hq];            // [dir] cell state (fp32)
// Recurrent weights, plain fp16, gate-interleaved, TRANSPOSED: [n=j*4+g][k]
__device__ __half g_Uhif[G4H * Hq];          // 8 MB
__device__ __half g_Uhib[G4H * Hq];
// hcat as split-fp16; row m = b*S+s, col = dir*H+j. Ahi is the A operand of
// the next recurrent step; Ahi+Alo feed the output GEMM.
__device__ __half g_Ahi[(size_t)Mout * Kout]; // 128 MB
__device__ __half g_Alo[(size_t)Mout * Kout]; // 128 MB
// Wd transposed, plain fp16: B[n][k] = Wd[k][n]
__device__ __half g_Bhi[Vq * Kout];          // 8 MB

// ---------------------------------------------------------------------------
// f32x2 packed-FMA helpers (embW precompute GEMM)
// ---------------------------------------------------------------------------
__device__ __forceinline__ unsigned long long dup2(float x) {
    unsigned long long r;
    asm("mov.b64 %0, {%1, %1};" : "=l"(r) : "f"(x));
    return r;
}
__device__ __forceinline__ void ffma2(unsigned long long &acc,
                                      unsigned long long a,
                                      unsigned long long b) {
    asm("fma.rn.f32x2 %0, %1, %2, %0;" : "+l"(acc) : "l"(a), "l"(b));
}
__device__ __forceinline__ float2 unpack2(unsigned long long v) {
    float2 f;
    asm("mov.b64 {%0, %1}, %2;" : "=f"(f.x), "=f"(f.y) : "l"(v));
    return f;
}
__device__ __forceinline__ float sigmoidf_fast(float x) {
    return __fdividef(1.f, 1.f + __expf(-x));
}
__device__ __forceinline__ unsigned smem_to_u32(const void* p) {
    unsigned a;
    asm("{ .reg .u64 t; cvta.to.shared.u64 t, %1; cvt.u32.u64 %0, t; }"
        : "=r"(a) : "l"(p));
    return a;
}

// ---------------------------------------------------------------------------
// sm_80+ portable async-copy + ldmatrix + HMMA (fp16, fp32 accumulate)
// ---------------------------------------------------------------------------
__device__ __forceinline__ void cp_async16(unsigned smem_addr, const void* gptr) {
    asm volatile("cp.async.cg.shared.global [%0], [%1], 16;"
                 :: "r"(smem_addr), "l"(gptr));
}
#define CP_COMMIT() asm volatile("cp.async.commit_group;" ::: "memory")
#define CP_WAIT(n)  asm volatile("cp.async.wait_group %0;" :: "n"(n) : "memory")

__device__ __forceinline__ void ldmatrix_x4(unsigned* r, unsigned addr) {
    asm volatile("ldmatrix.sync.aligned.m8n8.x4.shared.b16 {%0,%1,%2,%3}, [%4];"
                 : "=r"(r[0]), "=r"(r[1]), "=r"(r[2]), "=r"(r[3]) : "r"(addr));
}
__device__ __forceinline__ void mma_f16(float* c, const unsigned* a,
                                        const unsigned* b) {
    asm volatile(
        "mma.sync.aligned.m16n8k16.row.col.f32.f16.f16.f32 "
        "{%0,%1,%2,%3}, {%4,%5,%6,%7}, {%8,%9}, {%0,%1,%2,%3};"
        : "+f"(c[0]), "+f"(c[1]), "+f"(c[2]), "+f"(c[3])
        : "r"(a[0]), "r"(a[1]), "r"(a[2]), "r"(a[3]), "r"(b[0]), "r"(b[1]));
}

// ---------------------------------------------------------------------------
// Zero the cell state
// ---------------------------------------------------------------------------
__global__ void init_state_kernel() {
    int i = blockIdx.x * blockDim.x + threadIdx.x;
    if (i < Bq * Hq) { g_c[0][i] = 0.f; g_c[1][i] = 0.f; }
}

// ---------------------------------------------------------------------------
// Gate-interleave W, b:  Wt[e][j*4+g] = W[e][g*H+j]
// ---------------------------------------------------------------------------
__global__ void interleave_W_kernel(const float* __restrict__ Wf,
                                    const float* __restrict__ Wb,
                                    const float* __restrict__ bf,
                                    const float* __restrict__ bb) {
    int idx = blockIdx.x * blockDim.x + threadIdx.x;
    if (idx < Eq * G4H) {
        int e = idx >> 12;
        int c = idx & 4095;
        int src = e * G4H + (c & 3) * Hq + (c >> 2);
        g_Wtf[idx] = Wf[src];
        g_Wtb[idx] = Wb[src];
    }
    if (idx < G4H) {
        int src = (idx & 3) * Hq + (idx >> 2);
        g_btf[idx] = bf[src];
        g_btb[idx] = bb[src];
    }
}

// ---------------------------------------------------------------------------
// fp16 + transpose + gate-interleave U:  U16[dir][(j*4+g)][k] = fp16(U[k][g*H+j])
// ---------------------------------------------------------------------------
__global__ void split_transpose_U_kernel(const float* __restrict__ Uf,
                                         const float* __restrict__ Ub) {
    __shared__ float ts[32][33];
    int j0 = blockIdx.x * 32;
    int k0 = blockIdx.y * 32;
    int g   = blockIdx.z & 3;
    int dir = blockIdx.z >> 2;
    const float* U = dir ? Ub : Uf;
    __half* Dhi = dir ? g_Uhib : g_Uhif;
    int tx = threadIdx.x, ty = threadIdx.y;
#pragma unroll
    for (int i = 0; i < 32; i += 8)
        ts[ty + i][tx] = U[(size_t)(k0 + ty + i) * G4H + g * Hq + j0 + tx];
    __syncthreads();
#pragma unroll
    for (int i = 0; i < 32; i += 8) {
        int j = j0 + ty + i;
        float v = ts[tx][ty + i];          // U[k0+tx][g*H + j]
        size_t o = (size_t)((j << 2) + g) * Hq + k0 + tx;
        Dhi[o] = __float2half(v);
    }
}

// ---------------------------------------------------------------------------
// fp16 + transpose Wd:  Bhi[n][k] = fp16(Wd[k][n])
// ---------------------------------------------------------------------------
__global__ void split_transpose_Wd_kernel(const float* __restrict__ Wd) {
    __shared__ float ts[32][33];
    int n0 = blockIdx.x * 32;
    int k0 = blockIdx.y * 32;
    int tx = threadIdx.x, ty = threadIdx.y;
#pragma unroll
    for (int i = 0; i < 32; i += 8)
        ts[ty + i][tx] = Wd[(size_t)(k0 + ty + i) * Vq + n0 + tx];
    __syncthreads();
#pragma unroll
    for (int i = 0; i < 32; i += 8) {
        float v = ts[tx][ty + i];            // Wd[k0+tx][n0+ty+i]
        size_t o = (size_t)(n0 + ty + i) * Kout + k0 + tx;
        g_Bhi[o] = __float2half(v);
    }
}

// ---------------------------------------------------------------------------
// Generic tiled fp32 GEMM (embW precompute):  C = A @ B + bias
// ---------------------------------------------------------------------------
__global__ __launch_bounds__(256) void gemm_bias_kernel(
    const float* __restrict__ A, const float* __restrict__ B,
    const float* __restrict__ bias, float* __restrict__ C,
    int M, int N, int K)
{
    __shared__ float As[16][128];
    __shared__ float Bs[16][128];

    const int tid = threadIdx.x;
    const int n0  = blockIdx.x * 128;
    const int m0  = blockIdx.y * 128;

    const int a_kq = tid & 3;
    const int a_r  = tid >> 2;
    const int b_c4 = tid & 31;
    const int b_k  = tid >> 5;

    const int trow = tid >> 4;
    const int tcol = tid & 15;

    unsigned long long acc[4][8];
#pragma unroll
    for (int i = 0; i < 4; i++)
#pragma unroll
        for (int j = 0; j < 8; j++) acc[i][j] = 0ull;

    float4 pa0, pa1, pb0, pb1;
    pa0 = *reinterpret_cast<const float4*>(&A[(m0 + a_r)      * K + a_kq * 4]);
    pa1 = *reinterpret_cast<const float4*>(&A[(m0 + a_r + 64) * K + a_kq * 4]);
    pb0 = *reinterpret_cast<const float4*>(&B[(b_k)     * N + n0 + b_c4 * 4]);
    pb1 = *reinterpret_cast<const float4*>(&B[(b_k + 8) * N + n0 + b_c4 * 4]);

    for (int kc = 0; kc < K; kc += 16) {
        As[a_kq * 4 + 0][a_r] = pa0.x;
        As[a_kq * 4 + 1][a_r] = pa0.y;
        As[a_kq * 4 + 2][a_r] = pa0.z;
        As[a_kq * 4 + 3][a_r] = pa0.w;
        As[a_kq * 4 + 0][a_r + 64] = pa1.x;
        As[a_kq * 4 + 1][a_r + 64] = pa1.y;
        As[a_kq * 4 + 2][a_r + 64] = pa1.z;
        As[a_kq * 4 + 3][a_r + 64] = pa1.w;
        *reinterpret_cast<float4*>(&Bs[b_k][b_c4 * 4])     = pb0;
        *reinterpret_cast<float4*>(&Bs[b_k + 8][b_c4 * 4]) = pb1;
        __syncthreads();

        const int kn = kc + 16;
        if (kn < K) {
            pa0 = *reinterpret_cast<const float4*>(&A[(m0 + a_r)      * K + kn + a_kq * 4]);
            pa1 = *reinterpret_cast<const float4*>(&A[(m0 + a_r + 64) * K + kn + a_kq * 4]);
            pb0 = *reinterpret_cast<const float4*>(&B[(kn + b_k)     * N + n0 + b_c4 * 4]);
            pb1 = *reinterpret_cast<const float4*>(&B[(kn + b_k + 8) * N + n0 + b_c4 * 4]);
        }

#pragma unroll
        for (int k = 0; k < 16; k++) {
            const ulonglong2* ap =
                reinterpret_cast<const ulonglong2*>(&As[k][trow * 8]);
            ulonglong2 av0 = ap[0];
            ulonglong2 av1 = ap[1];
            unsigned long long a4[4] = {av0.x, av0.y, av1.x, av1.y};

            float4 bv0 = *reinterpret_cast<const float4*>(&Bs[k][tcol * 8]);
            float4 bv1 = *reinterpret_cast<const float4*>(&Bs[k][tcol * 8 + 4]);
            unsigned long long bd[8];
            bd[0] = dup2(bv0.x); bd[1] = dup2(bv0.y);
            bd[2] = dup2(bv0.z); bd[3] = dup2(bv0.w);
            bd[4] = dup2(bv1.x); bd[5] = dup2(bv1.y);
            bd[6] = dup2(bv1.z); bd[7] = dup2(bv1.w);

#pragma unroll
            for (int ip = 0; ip < 4; ip++)
#pragma unroll
                for (int j = 0; j < 8; j++)
                    ffma2(acc[ip][j], a4[ip], bd[j]);
        }
        __syncthreads();
    }

    float bsv[8];
#pragma unroll
    for (int j = 0; j < 8; j++) bsv[j] = bias[n0 + tcol * 8 + j];

#pragma unroll
    for (int ip = 0; ip < 4; ip++) {
        float2 v[8];
#pragma unroll
        for (int j = 0; j < 8; j++) v[j] = unpack2(acc[ip][j]);
        int r0 = m0 + trow * 8 + ip * 2;
        float* c0 = C + (size_t)r0 * N + n0 + tcol * 8;
        float* c1 = c0 + N;
        float4 x0 = make_float4(v[0].x + bsv[0], v[1].x + bsv[1],
                                v[2].x + bsv[2], v[3].x + bsv[3]);
        float4 x1 = make_float4(v[4].x + bsv[4], v[5].x + bsv[5],
                                v[6].x + bsv[6], v[7].x + bsv[7]);
        float4 y0 = make_float4(v[0].y + bsv[0], v[1].y + bsv[1],
                                v[2].y + bsv[2], v[3].y + bsv[3]);
        float4 y1 = make_float4(v[4].y + bsv[4], v[5].y + bsv[5],
                                v[6].y + bsv[6], v[7].y + bsv[7]);
        *reinterpret_cast<float4*>(c0)     = x0;
        *reinterpret_cast<float4*>(c0 + 4) = x1;
        *reinterpret_cast<float4*>(c1)     = y0;
        *reinterpret_cast<float4*>(c1 + 4) = y1;
    }
}

// ---------------------------------------------------------------------------
// One LSTM step via HMMA fp16, SINGLE-pass A:  z = A16 @ U16^T
// BK=64, 3-stage cp.async pipeline, 16 K-chunks.
// 512 threads (16 warps, 4m x 4n). CTA tile 64 batch x 128 interleaved cols.
// Grid (G4H/128=32, Bq/64=2, dir=2) = 128 CTAs.
// Row stride 144B: row offsets mod 128 hit 8 distinct 16B banks (conflict-free
// for ldmatrix and for the cp.async stores).
// ---------------------------------------------------------------------------
#define LS_RS     144                      // bytes per 64-fp16 SMEM row (+16 pad)
#define LS_ABYTES (64 * LS_RS)             // 9216
#define LS_BBYTES (128 * LS_RS)            // 18432
#define LS_STAGE  (LS_ABYTES + LS_BBYTES)  // 27648
#define LS_CHUNKS 16
#define LS_SMEM   (3 * LS_STAGE)           // 82944 (z-tile aliases this)

__global__ __launch_bounds__(512, 1) void lstm_mma_step_kernel(
    const int* __restrict__ tokens, int t)
{
    extern __shared__ char smem[];
    const unsigned sb = smem_to_u32(smem);
    float (*zs)[132] = reinterpret_cast<float (*)[132]>(smem);  // 64x132 fp32
    __shared__ int toks[64];

    const int tid = threadIdx.x;
    const int wid = tid >> 5;
    const int lane = tid & 31;
    const int warp_m = wid >> 2;        // 0..3 (16 rows each)
    const int warp_n = wid & 3;         // 0..3 (32 cols each)
    const int c0  = blockIdx.x * 128;   // interleaved col base
    const int b0  = blockIdx.y * 64;
    const int dir = blockIdx.z;
    const int s  = dir ? (Sq - 1 - t) : t;
    const int sp = dir ? (Sq - t) : (t - 1);   // previous step's s (t>0)

    const __half* Uhi = dir ? g_Uhib : g_Uhif;

    if (tid < 64) toks[tid] = tokens[(b0 + tid) * Sq + s];

    float acc[4][4];                    // [nt][quad]
#pragma unroll
    for (int nt = 0; nt < 4; nt++)
#pragma unroll
        for (int q = 0; q < 4; q++) acc[nt][q] = 0.f;

    if (t > 0) {
        auto issue_chunk = [&](int kc, int buf) {
            const unsigned bb = sb + buf * LS_STAGE;
#pragma unroll
            for (int i = 0; i < 3; i++) {
                int id = i * 512 + tid;            // 0..1535
                if (id < 512) {
                    int r = id >> 3, ch = id & 7;  // A: 64 rows x 8 chunks
                    unsigned dst = bb + r * LS_RS + ch * 16;
                    cp_async16(dst, g_Ahi +
                        ((size_t)(b0 + r) * Sq + sp) * Kout + dir * Hq + kc + ch * 8);
                } else {
                    int id2 = id - 512;            // 0..1023: U, 128 rows x 8
                    int r = id2 >> 3, ch = id2 & 7;
                    unsigned dst = bb + LS_ABYTES + r * LS_RS + ch * 16;
                    cp_async16(dst, Uhi + (size_t)(c0 + r) * Hq + kc + ch * 8);
                }
            }
            CP_COMMIT();
        };

        issue_chunk(0, 0);
        issue_chunk(64, 1);
        issue_chunk(128, 2);

        for (int c = 0; c < LS_CHUNKS; c++) {
            if (c < LS_CHUNKS - 2)      { CP_WAIT(2); }
            else if (c == LS_CHUNKS - 2){ CP_WAIT(1); }
            else                        { CP_WAIT(0); }
            __syncthreads();

            const unsigned bb  = sb + (c % 3) * LS_STAGE;
            const unsigned sAh = bb;
            const unsigned sBh = bb + LS_ABYTES;

#pragma unroll
            for (int kh = 0; kh < 4; kh++) {
                const int koff = kh * 32;          // bytes (16 fp16)
                const unsigned a_off =
                    (warp_m * 16 + (lane & 15)) * LS_RS + koff + ((lane >> 4) << 4);
                const unsigned b_off =
                    (warp_n * 32 + (lane & 7) + ((lane >> 4) << 3)) * LS_RS +
                    koff + (((lane >> 3) & 1) << 4);

                unsigned aH[4], bH[4][2];
                ldmatrix_x4(aH, sAh + a_off);
#pragma unroll
                for (int np = 0; np < 2; np++) {
                    unsigned r4[4];
                    ldmatrix_x4(r4, sBh + b_off + np * 16 * LS_RS);
                    bH[np * 2][0] = r4[0]; bH[np * 2][1] = r4[1];
                    bH[np * 2 + 1][0] = r4[2]; bH[np * 2 + 1][1] = r4[3];
                }

#pragma unroll
                for (int nt = 0; nt < 4; nt++)
                    mma_f16(acc[nt], aH, bH[nt]);
            }

            __syncthreads();
            if (c + 3 < LS_CHUNKS) issue_chunk((c + 3) * 64, c % 3);
        }
    }

    __syncthreads();   // all MMA reads done; safe to alias stage smem as zs

    // fragments -> z tile
    {
        int r = warp_m * 16 + (lane >> 2);
#pragma unroll
        for (int nt = 0; nt < 4; nt++) {
            int col = warp_n * 32 + nt * 8 + 2 * (lane & 3);
            *reinterpret_cast<float2*>(&zs[r][col]) =
                make_float2(acc[nt][0], acc[nt][1]);
            *reinterpret_cast<float2*>(&zs[r + 8][col]) =
                make_float2(acc[nt][2], acc[nt][3]);
        }
    }
    __syncthreads();

    // fused gate update: 64 rows x 32 hidden units = 2048 items / 512 threads
    const float* embW = dir ? g_embWtb : g_embWtf;
    float* cptr = &g_c[dir][0];
    const int j0q = c0 >> 2;

#pragma unroll
    for (int it = 0; it < 4; it++) {
        int idx = it * 512 + tid;
        int r  = idx >> 5;     // 0..63
        int jj = idx & 31;     // 0..31
        int j = j0q + jj;

        float4 z4 = *reinterpret_cast<const float4*>(&zs[r][jj * 4]);
        int tok = toks[r];
        float4 ew = *reinterpret_cast<const float4*>(
            &embW[(size_t)tok * G4H + (j << 2)]);
        float zi = z4.x + ew.x;
        float zf = z4.y + ew.y;
        float zg = z4.z + ew.z;
        float zo = z4.w + ew.w;

        float ig = sigmoidf_fast(zi);
        float fg = sigmoidf_fast(zf);
        float og = sigmoidf_fast(zo);
        float gg = dir ? fmaxf(zg, 0.f) : tanhf(zg);

        int ci = (b0 + r) * Hq + j;
        float cv = fg * cptr[ci] + ig * gg;
        cptr[ci] = cv;
        float hc = dir ? fmaxf(cv, 0.f) : tanhf(cv);
        float hv = og * hc;

        size_t ao = ((size_t)(b0 + r) * Sq + s) * Kout + dir * Hq + j;
        __half hi = __float2half(hv);
        g_Ahi[ao] = hi;
        g_Alo[ao] = __float2half(hv - __half2float(hi));
    }
}

// ---------------------------------------------------------------------------
// Output GEMM via HMMA fp16, 2-pass split-A (unchanged from R10, validated):
//   out[m][n] = (Ahi + Alo) @ Bhi^T + bd[n]
// ---------------------------------------------------------------------------
#define OG_BK       32
#define OG_CHUNKS   (Kout / OG_BK)      // 64
#define OG_RSTRIDE  80
#define OG_TILE_B   (128 * OG_RSTRIDE)  // 10240
#define OG_STAGE_B  (3 * OG_TILE_B)     // Ahi, Alo, Bhi
#define OG_SMEM     (2 * OG_STAGE_B)    // 61440

__global__ __launch_bounds__(256, 2) void out_gemm_kernel(
    const __half* __restrict__ Ahi, const __half* __restrict__ Alo,
    const __half* __restrict__ Bhi,
    const float* __restrict__ bd, float* __restrict__ out)
{
    extern __shared__ char smem[];
    const unsigned sb = smem_to_u32(smem);
    const int tid = threadIdx.x;
    const int wid = tid >> 5;
    const int lane = tid & 31;
    const int warp_m = wid >> 2;
    const int warp_n = wid & 3;
    const int n0 = blockIdx.x * 128;
    const int m0 = blockIdx.y * 128;

    const __half* srcs[3] = {Ahi, Alo, Bhi};
    const int rowbase[3] = {m0, m0, n0};

    auto issue_chunk = [&](int kc, int buf) {
        const unsigned bb = sb + buf * OG_STAGE_B;
#pragma unroll
        for (int i = 0; i < 6; i++) {
            int id   = i * 256 + tid;    // 0..1535
            int tile = id >> 9;          // 0..2
            int rem  = id & 511;
            int r    = rem >> 2;
            int ch   = rem & 3;
            unsigned dst = bb + tile * OG_TILE_B + r * OG_RSTRIDE + ch * 16;
            const void* g = srcs[tile] +
                            (size_t)(rowbase[tile] + r) * Kout + kc + ch * 8;
            cp_async16(dst, g);
        }
        CP_COMMIT();
    };

    float acc[4][4][4];
#pragma unroll
    for (int mt = 0; mt < 4; mt++)
#pragma unroll
        for (int nt = 0; nt < 4; nt++)
#pragma unroll
            for (int q = 0; q < 4; q++) acc[mt][nt][q] = 0.f;

    issue_chunk(0, 0);
    issue_chunk(OG_BK, 1);

    for (int c = 0; c < OG_CHUNKS; c++) {
        if (c < OG_CHUNKS - 1) { CP_WAIT(1); } else { CP_WAIT(0); }
        __syncthreads();

        const unsigned bb  = sb + (c & 1) * OG_STAGE_B;
        const unsigned sAh = bb;
        const unsigned sAl = bb + OG_TILE_B;
        const unsigned sBh = bb + 2 * OG_TILE_B;

#pragma unroll
        for (int kh = 0; kh < 2; kh++) {
            const int koff = kh * 32;
            const unsigned a_off =
                (warp_m * 64 + (lane & 15)) * OG_RSTRIDE + koff + ((lane >> 4) << 4);
            const unsigned b_off =
                (warp_n * 32 + (lane & 7) + ((lane >> 4) << 3)) * OG_RSTRIDE +
                koff + (((lane >> 3) & 1) << 4);

            unsigned aH[4][4], aL[4][4], bH[4][2];
#pragma unroll
            for (int mt = 0; mt < 4; mt++) {
                ldmatrix_x4(aH[mt], sAh + a_off + mt * 16 * OG_RSTRIDE);
                ldmatrix_x4(aL[mt], sAl + a_off + mt * 16 * OG_RSTRIDE);
            }
#pragma unroll
            for (int np = 0; np < 2; np++) {
                unsigned r4[4];
                ldmatrix_x4(r4, sBh + b_off + np * 16 * OG_RSTRIDE);
                bH[np * 2][0] = r4[0]; bH[np * 2][1] = r4[1];
                bH[np * 2 + 1][0] = r4[2]; bH[np * 2 + 1][1] = r4[3];
            }

#pragma unroll
            for (int mt = 0; mt < 4; mt++)
#pragma unroll
                for (int nt = 0; nt < 4; nt++) {
                    mma_f16(acc[mt][nt], aH[mt], bH[nt]);
                    mma_f16(acc[mt][nt], aL[mt], bH[nt]);
                }
        }

        __syncthreads();
        if (c + 2 < OG_CHUNKS) issue_chunk((c + 2) * OG_BK, c & 1);
    }

#pragma unroll
    for (int mt = 0; mt < 4; mt++) {
        int r0 = m0 + warp_m * 64 + mt * 16 + (lane >> 2);
#pragma unroll
        for (int nt = 0; nt < 4; nt++) {
            int col = n0 + warp_n * 32 + nt * 8 + 2 * (lane & 3);
            float b0v = bd[col], b1v = bd[col + 1];
            float2 v0 = make_float2(acc[mt][nt][0] + b0v, acc[mt][nt][1] + b1v);
            float2 v1 = make_float2(acc[mt][nt][2] + b0v, acc[mt][nt][3] + b1v);
            *reinterpret_cast<float2*>(out + (size_t)r0 * Vq + col) = v0;
            *reinterpret_cast<float2*>(out + (size_t)(r0 + 8) * Vq + col) = v1;
        }
    }
}

// ---------------------------------------------------------------------------
// Launch
// ---------------------------------------------------------------------------
extern "C" void kernel_launch(void* const* d_in, const int* in_sizes, int n_in,
                              void* d_out, int out_size) {
    (void)in_sizes; (void)n_in; (void)out_size;
    const int*   tokens = (const int*)  d_in[0];
    const float* emb    = (const float*)d_in[1];
    const float* Wf     = (const float*)d_in[2];
    const float* Uf     = (const float*)d_in[3];
    const float* bf     = (const float*)d_in[4];
    const float* Wb     = (const float*)d_in[5];
    const float* Ub     = (const float*)d_in[6];
    const float* bb     = (const float*)d_in[7];
    const float* Wd     = (const float*)d_in[8];
    const float* bd     = (const float*)d_in[9];
    float* out = (float*)d_out;

    float *p_Wtf, *p_Wtb, *p_btf, *p_btb, *p_embWtf, *p_embWtb;
    __half *p_Ahi, *p_Alo, *p_Bhi;
    cudaGetSymbolAddress((void**)&p_Wtf,    g_Wtf);
    cudaGetSymbolAddress((void**)&p_Wtb,    g_Wtb);
    cudaGetSymbolAddress((void**)&p_btf,    g_btf);
    cudaGetSymbolAddress((void**)&p_btb,    g_btb);
    cudaGetSymbolAddress((void**)&p_embWtf, g_embWtf);
    cudaGetSymbolAddress((void**)&p_embWtb, g_embWtb);
    cudaGetSymbolAddress((void**)&p_Ahi,    g_Ahi);
    cudaGetSymbolAddress((void**)&p_Alo,    g_Alo);
    cudaGetSymbolAddress((void**)&p_Bhi,    g_Bhi);

    cudaFuncSetAttribute(out_gemm_kernel,
                         cudaFuncAttributeMaxDynamicSharedMemorySize, OG_SMEM);
    cudaFuncSetAttribute(lstm_mma_step_kernel,
                         cudaFuncAttributeMaxDynamicSharedMemorySize, LS_SMEM);

    init_state_kernel<<<(Bq * Hq + 255) / 256, 256>>>();
    interleave_W_kernel<<<(Eq * G4H + 255) / 256, 256>>>(Wf, Wb, bf, bb);
    split_transpose_U_kernel<<<dim3(Hq / 32, Hq / 32, 8), dim3(32, 8)>>>(Uf, Ub);
    split_transpose_Wd_kernel<<<dim3(Vq / 32, Kout / 32), dim3(32, 8)>>>(Wd);

    // embWt = emb @ Wt + bt  (gate-interleaved, bias folded)
    gemm_bias_kernel<<<dim3(G4H / 128, Vq / 128), 256>>>(
        emb, p_Wtf, p_btf, p_embWtf, Vq, G4H, Eq);
    gemm_bias_kernel<<<dim3(G4H / 128, Vq / 128), 256>>>(
        emb, p_Wtb, p_btb, p_embWtb, Vq, G4H, Eq);

    // 256 sequential recurrent steps (both directions per launch), HMMA fp16
    for (int t = 0; t < Sq; t++) {
        lstm_mma_step_kernel<<<dim3(G4H / 128, Bq / 64, 2), 512, LS_SMEM>>>(
            tokens, t);
    }

    out_gemm_kernel<<<dim3(Vq / 128, Mout / 128), 256, OG_SMEM>>>(
        p_Ahi, p_Alo, p_Bhi, bd, out);
}

// round 13
// speedup vs baseline: 3.3493x; 1.7694x over previous
#include <cuda_runtime.h>
#include <cuda_fp16.h>
#include <math.h>

// Problem dims
#define Bq   128
#define Sq   256
#define Eq   512
#define Hq   1024
#define Vq   2048
#define G4H  4096   // 4*H
#define Kout 2048   // 2*H (output GEMM K)
#define Mout (Bq * Sq)

// ---------------------------------------------------------------------------
// Scratch (device globals; no allocation allowed)
// ---------------------------------------------------------------------------
__device__ float g_Wtf[Eq * G4H];            //  8 MB: Wf gate-interleaved
__device__ float g_Wtb[Eq * G4H];
__device__ float g_btf[G4H];
__device__ float g_btb[G4H];
__device__ float g_embWtf[Vq * G4H];         // 32 MB (bias folded)
__device__ float g_embWtb[Vq * G4H];
__device__ float g_c[2][Bq * Hq];            // [dir] cell state (fp32)
// Recurrent weights, plain fp16, gate-interleaved, TRANSPOSED: [n=j*4+g][k]
__device__ __half g_Uhif[G4H * Hq];          // 8 MB
__device__ __half g_Uhib[G4H * Hq];
// hcat fp16; row m = b*S+s, col = dir*H+j. A operand of the next recurrent
// step (rows at s_prev) and of the output GEMM.
__device__ __half g_Ahi[(size_t)Mout * Kout]; // 128 MB
// Wd transposed, plain fp16: B[n][k] = Wd[k][n]
__device__ __half g_Bhi[Vq * Kout];          // 8 MB

// ---------------------------------------------------------------------------
// f32x2 packed-FMA helpers (embW precompute GEMM)
// ---------------------------------------------------------------------------
__device__ __forceinline__ unsigned long long dup2(float x) {
    unsigned long long r;
    asm("mov.b64 %0, {%1, %1};" : "=l"(r) : "f"(x));
    return r;
}
__device__ __forceinline__ void ffma2(unsigned long long &acc,
                                      unsigned long long a,
                                      unsigned long long b) {
    asm("fma.rn.f32x2 %0, %1, %2, %0;" : "+l"(acc) : "l"(a), "l"(b));
}
__device__ __forceinline__ float2 unpack2(unsigned long long v) {
    float2 f;
    asm("mov.b64 {%0, %1}, %2;" : "=f"(f.x), "=f"(f.y) : "l"(v));
    return f;
}
__device__ __forceinline__ float sigmoidf_fast(float x) {
    return __fdividef(1.f, 1.f + __expf(-x));
}
__device__ __forceinline__ unsigned smem_to_u32(const void* p) {
    unsigned a;
    asm("{ .reg .u64 t; cvta.to.shared.u64 t, %1; cvt.u32.u64 %0, t; }"
        : "=r"(a) : "l"(p));
    return a;
}

// ---------------------------------------------------------------------------
// sm_80+ portable async-copy + ldmatrix + HMMA (fp16, fp32 accumulate)
// ---------------------------------------------------------------------------
__device__ __forceinline__ void cp_async16(unsigned smem_addr, const void* gptr) {
    asm volatile("cp.async.cg.shared.global [%0], [%1], 16;"
                 :: "r"(smem_addr), "l"(gptr));
}
#define CP_COMMIT() asm volatile("cp.async.commit_group;" ::: "memory")
#define CP_WAIT(n)  asm volatile("cp.async.wait_group %0;" :: "n"(n) : "memory")

__device__ __forceinline__ void ldmatrix_x4(unsigned* r, unsigned addr) {
    asm volatile("ldmatrix.sync.aligned.m8n8.x4.shared.b16 {%0,%1,%2,%3}, [%4];"
                 : "=r"(r[0]), "=r"(r[1]), "=r"(r[2]), "=r"(r[3]) : "r"(addr));
}
__device__ __forceinline__ void mma_f16(float* c, const unsigned* a,
                                        const unsigned* b) {
    asm volatile(
        "mma.sync.aligned.m16n8k16.row.col.f32.f16.f16.f32 "
        "{%0,%1,%2,%3}, {%4,%5,%6,%7}, {%8,%9}, {%0,%1,%2,%3};"
        : "+f"(c[0]), "+f"(c[1]), "+f"(c[2]), "+f"(c[3])
        : "r"(a[0]), "r"(a[1]), "r"(a[2]), "r"(a[3]), "r"(b[0]), "r"(b[1]));
}

// ---------------------------------------------------------------------------
// Zero the cell state
// ---------------------------------------------------------------------------
__global__ void init_state_kernel() {
    int i = blockIdx.x * blockDim.x + threadIdx.x;
    if (i < Bq * Hq) { g_c[0][i] = 0.f; g_c[1][i] = 0.f; }
}

// ---------------------------------------------------------------------------
// Gate-interleave W, b:  Wt[e][j*4+g] = W[e][g*H+j]
// ---------------------------------------------------------------------------
__global__ void interleave_W_kernel(const float* __restrict__ Wf,
                                    const float* __restrict__ Wb,
                                    const float* __restrict__ bf,
                                    const float* __restrict__ bb) {
    int idx = blockIdx.x * blockDim.x + threadIdx.x;
    if (idx < Eq * G4H) {
        int e = idx >> 12;
        int c = idx & 4095;
        int src = e * G4H + (c & 3) * Hq + (c >> 2);
        g_Wtf[idx] = Wf[src];
        g_Wtb[idx] = Wb[src];
    }
    if (idx < G4H) {
        int src = (idx & 3) * Hq + (idx >> 2);
        g_btf[idx] = bf[src];
        g_btb[idx] = bb[src];
    }
}

// ---------------------------------------------------------------------------
// fp16 + transpose + gate-interleave U:  U16[dir][(j*4+g)][k] = fp16(U[k][g*H+j])
// ---------------------------------------------------------------------------
__global__ void split_transpose_U_kernel(const float* __restrict__ Uf,
                                         const float* __restrict__ Ub) {
    __shared__ float ts[32][33];
    int j0 = blockIdx.x * 32;
    int k0 = blockIdx.y * 32;
    int g   = blockIdx.z & 3;
    int dir = blockIdx.z >> 2;
    const float* U = dir ? Ub : Uf;
    __half* Dhi = dir ? g_Uhib : g_Uhif;
    int tx = threadIdx.x, ty = threadIdx.y;
#pragma unroll
    for (int i = 0; i < 32; i += 8)
        ts[ty + i][tx] = U[(size_t)(k0 + ty + i) * G4H + g * Hq + j0 + tx];
    __syncthreads();
#pragma unroll
    for (int i = 0; i < 32; i += 8) {
        int j = j0 + ty + i;
        float v = ts[tx][ty + i];          // U[k0+tx][g*H + j]
        size_t o = (size_t)((j << 2) + g) * Hq + k0 + tx;
        Dhi[o] = __float2half(v);
    }
}

// ---------------------------------------------------------------------------
// fp16 + transpose Wd:  Bhi[n][k] = fp16(Wd[k][n])
// ---------------------------------------------------------------------------
__global__ void split_transpose_Wd_kernel(const float* __restrict__ Wd) {
    __shared__ float ts[32][33];
    int n0 = blockIdx.x * 32;
    int k0 = blockIdx.y * 32;
    int tx = threadIdx.x, ty = threadIdx.y;
#pragma unroll
    for (int i = 0; i < 32; i += 8)
        ts[ty + i][tx] = Wd[(size_t)(k0 + ty + i) * Vq + n0 + tx];
    __syncthreads();
#pragma unroll
    for (int i = 0; i < 32; i += 8) {
        float v = ts[tx][ty + i];            // Wd[k0+tx][n0+ty+i]
        size_t o = (size_t)(n0 + ty + i) * Kout + k0 + tx;
        g_Bhi[o] = __float2half(v);
    }
}

// ---------------------------------------------------------------------------
// Generic tiled fp32 GEMM (embW precompute):  C = A @ B + bias
// ---------------------------------------------------------------------------
__global__ __launch_bounds__(256) void gemm_bias_kernel(
    const float* __restrict__ A, const float* __restrict__ B,
    const float* __restrict__ bias, float* __restrict__ C,
    int M, int N, int K)
{
    __shared__ float As[16][128];
    __shared__ float Bs[16][128];

    const int tid = threadIdx.x;
    const int n0  = blockIdx.x * 128;
    const int m0  = blockIdx.y * 128;

    const int a_kq = tid & 3;
    const int a_r  = tid >> 2;
    const int b_c4 = tid & 31;
    const int b_k  = tid >> 5;

    const int trow = tid >> 4;
    const int tcol = tid & 15;

    unsigned long long acc[4][8];
#pragma unroll
    for (int i = 0; i < 4; i++)
#pragma unroll
        for (int j = 0; j < 8; j++) acc[i][j] = 0ull;

    float4 pa0, pa1, pb0, pb1;
    pa0 = *reinterpret_cast<const float4*>(&A[(m0 + a_r)      * K + a_kq * 4]);
    pa1 = *reinterpret_cast<const float4*>(&A[(m0 + a_r + 64) * K + a_kq * 4]);
    pb0 = *reinterpret_cast<const float4*>(&B[(b_k)     * N + n0 + b_c4 * 4]);
    pb1 = *reinterpret_cast<const float4*>(&B[(b_k + 8) * N + n0 + b_c4 * 4]);

    for (int kc = 0; kc < K; kc += 16) {
        As[a_kq * 4 + 0][a_r] = pa0.x;
        As[a_kq * 4 + 1][a_r] = pa0.y;
        As[a_kq * 4 + 2][a_r] = pa0.z;
        As[a_kq * 4 + 3][a_r] = pa0.w;
        As[a_kq * 4 + 0][a_r + 64] = pa1.x;
        As[a_kq * 4 + 1][a_r + 64] = pa1.y;
        As[a_kq * 4 + 2][a_r + 64] = pa1.z;
        As[a_kq * 4 + 3][a_r + 64] = pa1.w;
        *reinterpret_cast<float4*>(&Bs[b_k][b_c4 * 4])     = pb0;
        *reinterpret_cast<float4*>(&Bs[b_k + 8][b_c4 * 4]) = pb1;
        __syncthreads();

        const int kn = kc + 16;
        if (kn < K) {
            pa0 = *reinterpret_cast<const float4*>(&A[(m0 + a_r)      * K + kn + a_kq * 4]);
            pa1 = *reinterpret_cast<const float4*>(&A[(m0 + a_r + 64) * K + kn + a_kq * 4]);
            pb0 = *reinterpret_cast<const float4*>(&B[(kn + b_k)     * N + n0 + b_c4 * 4]);
            pb1 = *reinterpret_cast<const float4*>(&B[(kn + b_k + 8) * N + n0 + b_c4 * 4]);
        }

#pragma unroll
        for (int k = 0; k < 16; k++) {
            const ulonglong2* ap =
                reinterpret_cast<const ulonglong2*>(&As[k][trow * 8]);
            ulonglong2 av0 = ap[0];
            ulonglong2 av1 = ap[1];
            unsigned long long a4[4] = {av0.x, av0.y, av1.x, av1.y};

            float4 bv0 = *reinterpret_cast<const float4*>(&Bs[k][tcol * 8]);
            float4 bv1 = *reinterpret_cast<const float4*>(&Bs[k][tcol * 8 + 4]);
            unsigned long long bd[8];
            bd[0] = dup2(bv0.x); bd[1] = dup2(bv0.y);
            bd[2] = dup2(bv0.z); bd[3] = dup2(bv0.w);
            bd[4] = dup2(bv1.x); bd[5] = dup2(bv1.y);
            bd[6] = dup2(bv1.z); bd[7] = dup2(bv1.w);

#pragma unroll
            for (int ip = 0; ip < 4; ip++)
#pragma unroll
                for (int j = 0; j < 8; j++)
                    ffma2(acc[ip][j], a4[ip], bd[j]);
        }
        __syncthreads();
    }

    float bsv[8];
#pragma unroll
    for (int j = 0; j < 8; j++) bsv[j] = bias[n0 + tcol * 8 + j];

#pragma unroll
    for (int ip = 0; ip < 4; ip++) {
        float2 v[8];
#pragma unroll
        for (int j = 0; j < 8; j++) v[j] = unpack2(acc[ip][j]);
        int r0 = m0 + trow * 8 + ip * 2;
        float* c0 = C + (size_t)r0 * N + n0 + tcol * 8;
        float* c1 = c0 + N;
        float4 x0 = make_float4(v[0].x + bsv[0], v[1].x + bsv[1],
                                v[2].x + bsv[2], v[3].x + bsv[3]);
        float4 x1 = make_float4(v[4].x + bsv[4], v[5].x + bsv[5],
                                v[6].x + bsv[6], v[7].x + bsv[7]);
        float4 y0 = make_float4(v[0].y + bsv[0], v[1].y + bsv[1],
                                v[2].y + bsv[2], v[3].y + bsv[3]);
        float4 y1 = make_float4(v[4].y + bsv[4], v[5].y + bsv[5],
                                v[6].y + bsv[6], v[7].y + bsv[7]);
        *reinterpret_cast<float4*>(c0)     = x0;
        *reinterpret_cast<float4*>(c0 + 4) = x1;
        *reinterpret_cast<float4*>(c1)     = y0;
        *reinterpret_cast<float4*>(c1 + 4) = y1;
    }
}

// ---------------------------------------------------------------------------
// One LSTM step via HMMA fp16:  z = A16 @ U16^T
// BK=128, 3-stage cp.async pipeline, 8 K-chunks.
// 512 threads (16 warps, 4m x 4n). CTA tile 64 batch x 128 interleaved cols.
// Grid (G4H/128=32, Bq/64=2, dir=2) = 128 CTAs.
// Row stride 272B: row offsets mod 128 step by 16B -> 8 distinct 16B banks
// per 8-row ldmatrix matrix (conflict-free).
// ---------------------------------------------------------------------------
#define LS_RS     272                      // bytes per 128-fp16 SMEM row (+16 pad)
#define LS_ABYTES (64 * LS_RS)             // 17408
#define LS_BBYTES (128 * LS_RS)            // 34816
#define LS_STAGE  (LS_ABYTES + LS_BBYTES)  // 52224
#define LS_CHUNKS 8
#define LS_SMEM   (3 * LS_STAGE)           // 156672 (z-tile aliases this)

__global__ __launch_bounds__(512, 1) void lstm_mma_step_kernel(
    const int* __restrict__ tokens, int t)
{
    extern __shared__ char smem[];
    const unsigned sb = smem_to_u32(smem);
    float (*zs)[132] = reinterpret_cast<float (*)[132]>(smem);  // 64x132 fp32
    __shared__ int toks[64];

    const int tid = threadIdx.x;
    const int wid = tid >> 5;
    const int lane = tid & 31;
    const int warp_m = wid >> 2;        // 0..3 (16 rows each)
    const int warp_n = wid & 3;         // 0..3 (32 cols each)
    const int c0  = blockIdx.x * 128;   // interleaved col base
    const int b0  = blockIdx.y * 64;
    const int dir = blockIdx.z;
    const int s  = dir ? (Sq - 1 - t) : t;
    const int sp = dir ? (Sq - t) : (t - 1);   // previous step's s (t>0)

    const __half* Uhi = dir ? g_Uhib : g_Uhif;

    if (tid < 64) toks[tid] = tokens[(b0 + tid) * Sq + s];

    float acc[4][4];                    // [nt][quad]
#pragma unroll
    for (int nt = 0; nt < 4; nt++)
#pragma unroll
        for (int q = 0; q < 4; q++) acc[nt][q] = 0.f;

    if (t > 0) {
        auto issue_chunk = [&](int kc, int buf) {
            const unsigned bb = sb + buf * LS_STAGE;
#pragma unroll
            for (int i = 0; i < 6; i++) {
                int id = i * 512 + tid;            // 0..3071
                if (id < 1024) {
                    int r = id >> 4, ch = id & 15; // A: 64 rows x 16 chunks
                    unsigned dst = bb + r * LS_RS + ch * 16;
                    cp_async16(dst, g_Ahi +
                        ((size_t)(b0 + r) * Sq + sp) * Kout + dir * Hq + kc + ch * 8);
                } else {
                    int id2 = id - 1024;           // 0..2047: U, 128 rows x 16
                    int r = id2 >> 4, ch = id2 & 15;
                    unsigned dst = bb + LS_ABYTES + r * LS_RS + ch * 16;
                    cp_async16(dst, Uhi + (size_t)(c0 + r) * Hq + kc + ch * 8);
                }
            }
            CP_COMMIT();
        };

        issue_chunk(0, 0);
        issue_chunk(128, 1);
        issue_chunk(256, 2);

        for (int c = 0; c < LS_CHUNKS; c++) {
            if (c < LS_CHUNKS - 2)      { CP_WAIT(2); }
            else if (c == LS_CHUNKS - 2){ CP_WAIT(1); }
            else                        { CP_WAIT(0); }
            __syncthreads();

            const unsigned bb  = sb + (c % 3) * LS_STAGE;
            const unsigned sAh = bb;
            const unsigned sBh = bb + LS_ABYTES;

#pragma unroll
            for (int kh = 0; kh < 8; kh++) {
                const int koff = kh * 32;          // bytes (16 fp16)
                const unsigned a_off =
                    (warp_m * 16 + (lane & 15)) * LS_RS + koff + ((lane >> 4) << 4);
                const unsigned b_off =
                    (warp_n * 32 + (lane & 7) + ((lane >> 4) << 3)) * LS_RS +
                    koff + (((lane >> 3) & 1) << 4);

                unsigned aH[4], bH[4][2];
                ldmatrix_x4(aH, sAh + a_off);
#pragma unroll
                for (int np = 0; np < 2; np++) {
                    unsigned r4[4];
                    ldmatrix_x4(r4, sBh + b_off + np * 16 * LS_RS);
                    bH[np * 2][0] = r4[0]; bH[np * 2][1] = r4[1];
                    bH[np * 2 + 1][0] = r4[2]; bH[np * 2 + 1][1] = r4[3];
                }

#pragma unroll
                for (int nt = 0; nt < 4; nt++)
                    mma_f16(acc[nt], aH, bH[nt]);
            }

            __syncthreads();
            if (c + 3 < LS_CHUNKS) issue_chunk((c + 3) * 128, c % 3);
        }
    }

    __syncthreads();   // all MMA reads done; safe to alias stage smem as zs

    // fragments -> z tile
    {
        int r = warp_m * 16 + (lane >> 2);
#pragma unroll
        for (int nt = 0; nt < 4; nt++) {
            int col = warp_n * 32 + nt * 8 + 2 * (lane & 3);
            *reinterpret_cast<float2*>(&zs[r][col]) =
                make_float2(acc[nt][0], acc[nt][1]);
            *reinterpret_cast<float2*>(&zs[r + 8][col]) =
                make_float2(acc[nt][2], acc[nt][3]);
        }
    }
    __syncthreads();

    // fused gate update: 64 rows x 32 hidden units = 2048 items / 512 threads
    const float* embW = dir ? g_embWtb : g_embWtf;
    float* cptr = &g_c[dir][0];
    const int j0q = c0 >> 2;

#pragma unroll
    for (int it = 0; it < 4; it++) {
        int idx = it * 512 + tid;
        int r  = idx >> 5;     // 0..63
        int jj = idx & 31;     // 0..31
        int j = j0q + jj;

        float4 z4 = *reinterpret_cast<const float4*>(&zs[r][jj * 4]);
        int tok = toks[r];
        float4 ew = *reinterpret_cast<const float4*>(
            &embW[(size_t)tok * G4H + (j << 2)]);
        float zi = z4.x + ew.x;
        float zf = z4.y + ew.y;
        float zg = z4.z + ew.z;
        float zo = z4.w + ew.w;

        float ig = sigmoidf_fast(zi);
        float fg = sigmoidf_fast(zf);
        float og = sigmoidf_fast(zo);
        float gg = dir ? fmaxf(zg, 0.f) : tanhf(zg);

        int ci = (b0 + r) * Hq + j;
        float cv = fg * cptr[ci] + ig * gg;
        cptr[ci] = cv;
        float hc = dir ? fmaxf(cv, 0.f) : tanhf(cv);
        float hv = og * hc;

        size_t ao = ((size_t)(b0 + r) * Sq + s) * Kout + dir * Hq + j;
        g_Ahi[ao] = __float2half(hv);
    }
}

// ---------------------------------------------------------------------------
// Output GEMM via HMMA fp16, single-pass:
//   out[m][n] = A16 @ B16^T + bd[n]
// BK=64, 32 chunks, 2-stage. launch_bounds(256,2): 2 CTAs/SM (2 x 72KB smem).
// ---------------------------------------------------------------------------
#define OG_BK       64
#define OG_CHUNKS   (Kout / OG_BK)      // 32
#define OG_RS       144                 // bytes per 64-fp16 row (+16 pad)
#define OG_TILE_B   (128 * OG_RS)       // 18432
#define OG_STAGE_B  (2 * OG_TILE_B)     // A, B
#define OG_SMEM     (2 * OG_STAGE_B)    // 73728

__global__ __launch_bounds__(256, 2) void out_gemm_kernel(
    const __half* __restrict__ Ahi, const __half* __restrict__ Bhi,
    const float* __restrict__ bd, float* __restrict__ out)
{
    extern __shared__ char smem[];
    const unsigned sb = smem_to_u32(smem);
    const int tid = threadIdx.x;
    const int wid = tid >> 5;
    const int lane = tid & 31;
    const int warp_m = wid >> 2;
    const int warp_n = wid & 3;
    const int n0 = blockIdx.x * 128;
    const int m0 = blockIdx.y * 128;

    const __half* srcs[2] = {Ahi, Bhi};
    const int rowbase[2] = {m0, n0};

    auto issue_chunk = [&](int kc, int buf) {
        const unsigned bb = sb + buf * OG_STAGE_B;
#pragma unroll
        for (int i = 0; i < 8; i++) {
            int id   = i * 256 + tid;    // 0..2047
            int tile = id >> 10;         // 0..1
            int rem  = id & 1023;
            int r    = rem >> 3;         // 0..127
            int ch   = rem & 7;          // 16B chunk within 128B row
            unsigned dst = bb + tile * OG_TILE_B + r * OG_RS + ch * 16;
            const void* g = srcs[tile] +
                            (size_t)(rowbase[tile] + r) * Kout + kc + ch * 8;
            cp_async16(dst, g);
        }
        CP_COMMIT();
    };

    float acc[4][4][4];
#pragma unroll
    for (int mt = 0; mt < 4; mt++)
#pragma unroll
        for (int nt = 0; nt < 4; nt++)
#pragma unroll
            for (int q = 0; q < 4; q++) acc[mt][nt][q] = 0.f;

    issue_chunk(0, 0);
    issue_chunk(OG_BK, 1);

    for (int c = 0; c < OG_CHUNKS; c++) {
        if (c < OG_CHUNKS - 1) { CP_WAIT(1); } else { CP_WAIT(0); }
        __syncthreads();

        const unsigned bb  = sb + (c & 1) * OG_STAGE_B;
        const unsigned sAh = bb;
        const unsigned sBh = bb + OG_TILE_B;

#pragma unroll
        for (int kh = 0; kh < 4; kh++) {
            const int koff = kh * 32;
            const unsigned a_off =
                (warp_m * 64 + (lane & 15)) * OG_RS + koff + ((lane >> 4) << 4);
            const unsigned b_off =
                (warp_n * 32 + (lane & 7) + ((lane >> 4) << 3)) * OG_RS +
                koff + (((lane >> 3) & 1) << 4);

            unsigned aH[4][4], bH[4][2];
#pragma unroll
            for (int mt = 0; mt < 4; mt++)
                ldmatrix_x4(aH[mt], sAh + a_off + mt * 16 * OG_RS);
#pragma unroll
            for (int np = 0; np < 2; np++) {
                unsigned r4[4];
                ldmatrix_x4(r4, sBh + b_off + np * 16 * OG_RS);
                bH[np * 2][0] = r4[0]; bH[np * 2][1] = r4[1];
                bH[np * 2 + 1][0] = r4[2]; bH[np * 2 + 1][1] = r4[3];
            }

#pragma unroll
            for (int mt = 0; mt < 4; mt++)
#pragma unroll
                for (int nt = 0; nt < 4; nt++)
                    mma_f16(acc[mt][nt], aH[mt], bH[nt]);
        }

        __syncthreads();
        if (c + 2 < OG_CHUNKS) issue_chunk((c + 2) * OG_BK, c & 1);
    }

#pragma unroll
    for (int mt = 0; mt < 4; mt++) {
        int r0 = m0 + warp_m * 64 + mt * 16 + (lane >> 2);
#pragma unroll
        for (int nt = 0; nt < 4; nt++) {
            int col = n0 + warp_n * 32 + nt * 8 + 2 * (lane & 3);
            float b0v = bd[col], b1v = bd[col + 1];
            float2 v0 = make_float2(acc[mt][nt][0] + b0v, acc[mt][nt][1] + b1v);
            float2 v1 = make_float2(acc[mt][nt][2] + b0v, acc[mt][nt][3] + b1v);
            *reinterpret_cast<float2*>(out + (size_t)r0 * Vq + col) = v0;
            *reinterpret_cast<float2*>(out + (size_t)(r0 + 8) * Vq + col) = v1;
        }
    }
}

// ---------------------------------------------------------------------------
// Launch
// ---------------------------------------------------------------------------
extern "C" void kernel_launch(void* const* d_in, const int* in_sizes, int n_in,
                              void* d_out, int out_size) {
    (void)in_sizes; (void)n_in; (void)out_size;
    const int*   tokens = (const int*)  d_in[0];
    const float* emb    = (const float*)d_in[1];
    const float* Wf     = (const float*)d_in[2];
    const float* Uf     = (const float*)d_in[3];
    const float* bf     = (const float*)d_in[4];
    const float* Wb     = (const float*)d_in[5];
    const float* Ub     = (const float*)d_in[6];
    const float* bb     = (const float*)d_in[7];
    const float* Wd     = (const float*)d_in[8];
    const float* bd     = (const float*)d_in[9];
    float* out = (float*)d_out;

    float *p_Wtf, *p_Wtb, *p_btf, *p_btb, *p_embWtf, *p_embWtb;
    __half *p_Ahi, *p_Bhi;
    cudaGetSymbolAddress((void**)&p_Wtf,    g_Wtf);
    cudaGetSymbolAddress((void**)&p_Wtb,    g_Wtb);
    cudaGetSymbolAddress((void**)&p_btf,    g_btf);
    cudaGetSymbolAddress((void**)&p_btb,    g_btb);
    cudaGetSymbolAddress((void**)&p_embWtf, g_embWtf);
    cudaGetSymbolAddress((void**)&p_embWtb, g_embWtb);
    cudaGetSymbolAddress((void**)&p_Ahi,    g_Ahi);
    cudaGetSymbolAddress((void**)&p_Bhi,    g_Bhi);

    cudaFuncSetAttribute(out_gemm_kernel,
                         cudaFuncAttributeMaxDynamicSharedMemorySize, OG_SMEM);
    cudaFuncSetAttribute(lstm_mma_step_kernel,
                         cudaFuncAttributeMaxDynamicSharedMemorySize, LS_SMEM);

    init_state_kernel<<<(Bq * Hq + 255) / 256, 256>>>();
    interleave_W_kernel<<<(Eq * G4H + 255) / 256, 256>>>(Wf, Wb, bf, bb);
    split_transpose_U_kernel<<<dim3(Hq / 32, Hq / 32, 8), dim3(32, 8)>>>(Uf, Ub);
    split_transpose_Wd_kernel<<<dim3(Vq / 32, Kout / 32), dim3(32, 8)>>>(Wd);

    // embWt = emb @ Wt + bt  (gate-interleaved, bias folded)
    gemm_bias_kernel<<<dim3(G4H / 128, Vq / 128), 256>>>(
        emb, p_Wtf, p_btf, p_embWtf, Vq, G4H, Eq);
    gemm_bias_kernel<<<dim3(G4H / 128, Vq / 128), 256>>>(
        emb, p_Wtb, p_btb, p_embWtb, Vq, G4H, Eq);

    // 256 sequential recurrent steps (both directions per launch), HMMA fp16
    for (int t = 0; t < Sq; t++) {
        lstm_mma_step_kernel<<<dim3(G4H / 128, Bq / 64, 2), 512, LS_SMEM>>>(
            tokens, t);
    }

    out_gemm_kernel<<<dim3(Vq / 128, Mout / 128), 256, OG_SMEM>>>(
        p_Ahi, p_Bhi, bd, out);
}

// round 14
// speedup vs baseline: 3.5326x; 1.0547x over previous
#include <cuda_runtime.h>
#include <cuda_fp16.h>
#include <math.h>

// Problem dims
#define Bq   128
#define Sq   256
#define Eq   512
#define Hq   1024
#define Vq   2048
#define G4H  4096   // 4*H
#define Kout 2048   // 2*H (output GEMM K)
#define Mout (Bq * Sq)

// ---------------------------------------------------------------------------
// Scratch (device globals; no allocation allowed)
// ---------------------------------------------------------------------------
__device__ float g_btf[G4H];
__device__ float g_btb[G4H];
__device__ float g_embWtf[Vq * G4H];         // 32 MB (bias folded)
__device__ float g_embWtb[Vq * G4H];
__device__ float g_c[2][Bq * Hq];            // [dir] cell state (fp32)
__device__ __half g_emb16[Vq * Eq];          // 2 MB: emb in fp16
// W fp16, gate-interleaved, TRANSPOSED: [c=j*4+g][e]
__device__ __half g_Wt16f[G4H * Eq];         // 4 MB
__device__ __half g_Wt16b[G4H * Eq];
// Recurrent weights, plain fp16, gate-interleaved, TRANSPOSED: [n=j*4+g][k]
__device__ __half g_Uhif[G4H * Hq];          // 8 MB
__device__ __half g_Uhib[G4H * Hq];
// hcat fp16; row m = b*S+s, col = dir*H+j. A operand of the next recurrent
// step (rows at s_prev) and of the output GEMM.
__device__ __half g_Ahi[(size_t)Mout * Kout]; // 128 MB
// Wd transposed, plain fp16: B[n][k] = Wd[k][n]
__device__ __half g_Bhi[Vq * Kout];          // 8 MB

// ---------------------------------------------------------------------------
// Small helpers
// ---------------------------------------------------------------------------
__device__ __forceinline__ float sigmoidf_fast(float x) {
    return __fdividef(1.f, 1.f + __expf(-x));
}
__device__ __forceinline__ unsigned smem_to_u32(const void* p) {
    unsigned a;
    asm("{ .reg .u64 t; cvta.to.shared.u64 t, %1; cvt.u32.u64 %0, t; }"
        : "=r"(a) : "l"(p));
    return a;
}

// ---------------------------------------------------------------------------
// sm_80+ portable async-copy + ldmatrix + HMMA (fp16, fp32 accumulate)
// ---------------------------------------------------------------------------
__device__ __forceinline__ void cp_async16(unsigned smem_addr, const void* gptr) {
    asm volatile("cp.async.cg.shared.global [%0], [%1], 16;"
                 :: "r"(smem_addr), "l"(gptr));
}
#define CP_COMMIT() asm volatile("cp.async.commit_group;" ::: "memory")
#define CP_WAIT(n)  asm volatile("cp.async.wait_group %0;" :: "n"(n) : "memory")

__device__ __forceinline__ void ldmatrix_x4(unsigned* r, unsigned addr) {
    asm volatile("ldmatrix.sync.aligned.m8n8.x4.shared.b16 {%0,%1,%2,%3}, [%4];"
                 : "=r"(r[0]), "=r"(r[1]), "=r"(r[2]), "=r"(r[3]) : "r"(addr));
}
__device__ __forceinline__ void mma_f16(float* c, const unsigned* a,
                                        const unsigned* b) {
    asm volatile(
        "mma.sync.aligned.m16n8k16.row.col.f32.f16.f16.f32 "
        "{%0,%1,%2,%3}, {%4,%5,%6,%7}, {%8,%9}, {%0,%1,%2,%3};"
        : "+f"(c[0]), "+f"(c[1]), "+f"(c[2]), "+f"(c[3])
        : "r"(a[0]), "r"(a[1]), "r"(a[2]), "r"(a[3]), "r"(b[0]), "r"(b[1]));
}

// ---------------------------------------------------------------------------
// Zero the cell state + fp16 emb conversion
// ---------------------------------------------------------------------------
__global__ void init_state_kernel(const float* __restrict__ emb) {
    int i = blockIdx.x * blockDim.x + threadIdx.x;
    if (i < Bq * Hq) { g_c[0][i] = 0.f; g_c[1][i] = 0.f; }
    if (i < Vq * Eq) g_emb16[i] = __float2half(emb[i]);
}

// ---------------------------------------------------------------------------
// Gate-interleave biases:  bt[j*4+g] = b[g*H+j]
// ---------------------------------------------------------------------------
__global__ void interleave_b_kernel(const float* __restrict__ bf,
                                    const float* __restrict__ bb) {
    int idx = blockIdx.x * blockDim.x + threadIdx.x;
    if (idx < G4H) {
        int src = (idx & 3) * Hq + (idx >> 2);
        g_btf[idx] = bf[src];
        g_btb[idx] = bb[src];
    }
}

// ---------------------------------------------------------------------------
// fp16 + transpose + gate-interleave W:  Wt16[dir][(j*4+g)][e] = fp16(W[e][g*H+j])
// grid (Hq/32=32, Eq/32=16, 8 = dir*4+g), block (32,8)
// ---------------------------------------------------------------------------
__global__ void transpose_W16_kernel(const float* __restrict__ Wf,
                                     const float* __restrict__ Wb) {
    __shared__ float ts[32][33];
    int j0 = blockIdx.x * 32;
    int e0 = blockIdx.y * 32;
    int g   = blockIdx.z & 3;
    int dir = blockIdx.z >> 2;
    const float* W = dir ? Wb : Wf;
    __half* D = dir ? g_Wt16b : g_Wt16f;
    int tx = threadIdx.x, ty = threadIdx.y;
#pragma unroll
    for (int i = 0; i < 32; i += 8)
        ts[ty + i][tx] = W[(size_t)(e0 + ty + i) * G4H + g * Hq + j0 + tx];
    __syncthreads();
#pragma unroll
    for (int i = 0; i < 32; i += 8) {
        int j = j0 + ty + i;
        float v = ts[tx][ty + i];          // W[e0+tx][g*H + j]
        size_t o = (size_t)((j << 2) + g) * Eq + e0 + tx;
        D[o] = __float2half(v);
    }
}

// ---------------------------------------------------------------------------
// fp16 + transpose + gate-interleave U:  U16[dir][(j*4+g)][k] = fp16(U[k][g*H+j])
// ---------------------------------------------------------------------------
__global__ void split_transpose_U_kernel(const float* __restrict__ Uf,
                                         const float* __restrict__ Ub) {
    __shared__ float ts[32][33];
    int j0 = blockIdx.x * 32;
    int k0 = blockIdx.y * 32;
    int g   = blockIdx.z & 3;
    int dir = blockIdx.z >> 2;
    const float* U = dir ? Ub : Uf;
    __half* Dhi = dir ? g_Uhib : g_Uhif;
    int tx = threadIdx.x, ty = threadIdx.y;
#pragma unroll
    for (int i = 0; i < 32; i += 8)
        ts[ty + i][tx] = U[(size_t)(k0 + ty + i) * G4H + g * Hq + j0 + tx];
    __syncthreads();
#pragma unroll
    for (int i = 0; i < 32; i += 8) {
        int j = j0 + ty + i;
        float v = ts[tx][ty + i];          // U[k0+tx][g*H + j]
        size_t o = (size_t)((j << 2) + g) * Hq + k0 + tx;
        Dhi[o] = __float2half(v);
    }
}

// ---------------------------------------------------------------------------
// fp16 + transpose Wd:  Bhi[n][k] = fp16(Wd[k][n])
// ---------------------------------------------------------------------------
__global__ void split_transpose_Wd_kernel(const float* __restrict__ Wd) {
    __shared__ float ts[32][33];
    int n0 = blockIdx.x * 32;
    int k0 = blockIdx.y * 32;
    int tx = threadIdx.x, ty = threadIdx.y;
#pragma unroll
    for (int i = 0; i < 32; i += 8)
        ts[ty + i][tx] = Wd[(size_t)(k0 + ty + i) * Vq + n0 + tx];
    __syncthreads();
#pragma unroll
    for (int i = 0; i < 32; i += 8) {
        float v = ts[tx][ty + i];            // Wd[k0+tx][n0+ty+i]
        size_t o = (size_t)(n0 + ty + i) * Kout + k0 + tx;
        g_Bhi[o] = __float2half(v);
    }
}

// ---------------------------------------------------------------------------
// Generic fp16 HMMA GEMM with fp32 bias + fp32 output:
//   out[m][n] = A16[m][:] . B16[n][:] + bias[n]    (A: MxK, B: NxK, both
//   row-major with row stride K; out row stride = ldout)
// CTA tile 128x128, BK=64, runtime chunk count K/64, 2-stage cp.async.
// launch_bounds(256,2): 2 CTAs/SM (2 x 72KB smem).
// Used for both the output GEMM (K=2048) and the embW precompute (K=512).
// ---------------------------------------------------------------------------
#define OG_BK       64
#define OG_RS       144                 // bytes per 64-fp16 row (+16 pad)
#define OG_TILE_B   (128 * OG_RS)       // 18432
#define OG_STAGE_B  (2 * OG_TILE_B)     // A, B
#define OG_SMEM     (2 * OG_STAGE_B)    // 73728

__global__ __launch_bounds__(256, 2) void hgemm_bias_kernel(
    const __half* __restrict__ A, const __half* __restrict__ B,
    const float* __restrict__ bias, float* __restrict__ out,
    int K, int ldout)
{
    extern __shared__ char smem[];
    const unsigned sb = smem_to_u32(smem);
    const int tid = threadIdx.x;
    const int wid = tid >> 5;
    const int lane = tid & 31;
    const int warp_m = wid >> 2;
    const int warp_n = wid & 3;
    const int n0 = blockIdx.x * 128;
    const int m0 = blockIdx.y * 128;
    const int chunks = K >> 6;

    const __half* srcs[2] = {A, B};
    const int rowbase[2] = {m0, n0};

    auto issue_chunk = [&](int kc, int buf) {
        const unsigned bb = sb + buf * OG_STAGE_B;
#pragma unroll
        for (int i = 0; i < 8; i++) {
            int id   = i * 256 + tid;    // 0..2047
            int tile = id >> 10;         // 0..1
            int rem  = id & 1023;
            int r    = rem >> 3;         // 0..127
            int ch   = rem & 7;          // 16B chunk within 128B row
            unsigned dst = bb + tile * OG_TILE_B + r * OG_RS + ch * 16;
            const void* g = srcs[tile] +
                            (size_t)(rowbase[tile] + r) * K + kc + ch * 8;
            cp_async16(dst, g);
        }
        CP_COMMIT();
    };

    float acc[4][4][4];
#pragma unroll
    for (int mt = 0; mt < 4; mt++)
#pragma unroll
        for (int nt = 0; nt < 4; nt++)
#pragma unroll
            for (int q = 0; q < 4; q++) acc[mt][nt][q] = 0.f;

    issue_chunk(0, 0);
    issue_chunk(OG_BK, 1);

    for (int c = 0; c < chunks; c++) {
        if (c < chunks - 1) { CP_WAIT(1); } else { CP_WAIT(0); }
        __syncthreads();

        const unsigned bb  = sb + (c & 1) * OG_STAGE_B;
        const unsigned sAh = bb;
        const unsigned sBh = bb + OG_TILE_B;

#pragma unroll
        for (int kh = 0; kh < 4; kh++) {
            const int koff = kh * 32;
            const unsigned a_off =
                (warp_m * 64 + (lane & 15)) * OG_RS + koff + ((lane >> 4) << 4);
            const unsigned b_off =
                (warp_n * 32 + (lane & 7) + ((lane >> 4) << 3)) * OG_RS +
                koff + (((lane >> 3) & 1) << 4);

            unsigned aH[4][4], bH[4][2];
#pragma unroll
            for (int mt = 0; mt < 4; mt++)
                ldmatrix_x4(aH[mt], sAh + a_off + mt * 16 * OG_RS);
#pragma unroll
            for (int np = 0; np < 2; np++) {
                unsigned r4[4];
                ldmatrix_x4(r4, sBh + b_off + np * 16 * OG_RS);
                bH[np * 2][0] = r4[0]; bH[np * 2][1] = r4[1];
                bH[np * 2 + 1][0] = r4[2]; bH[np * 2 + 1][1] = r4[3];
            }

#pragma unroll
            for (int mt = 0; mt < 4; mt++)
#pragma unroll
                for (int nt = 0; nt < 4; nt++)
                    mma_f16(acc[mt][nt], aH[mt], bH[nt]);
        }

        __syncthreads();
        if (c + 2 < chunks) issue_chunk((c + 2) * OG_BK, c & 1);
    }

#pragma unroll
    for (int mt = 0; mt < 4; mt++) {
        int r0 = m0 + warp_m * 64 + mt * 16 + (lane >> 2);
#pragma unroll
        for (int nt = 0; nt < 4; nt++) {
            int col = n0 + warp_n * 32 + nt * 8 + 2 * (lane & 3);
            float b0v = bias[col], b1v = bias[col + 1];
            float2 v0 = make_float2(acc[mt][nt][0] + b0v, acc[mt][nt][1] + b1v);
            float2 v1 = make_float2(acc[mt][nt][2] + b0v, acc[mt][nt][3] + b1v);
            *reinterpret_cast<float2*>(out + (size_t)r0 * ldout + col) = v0;
            *reinterpret_cast<float2*>(out + (size_t)(r0 + 8) * ldout + col) = v1;
        }
    }
}

// ---------------------------------------------------------------------------
// One LSTM step via HMMA fp16:  z = A16 @ U16^T
// BK=256, 2-stage cp.async pipeline, 4 K-chunks.
// 512 threads (16 warps, 4m x 4n). CTA tile 64 batch x 128 interleaved cols.
// Grid (G4H/128=32, Bq/64=2, dir=2) = 128 CTAs.
// Row stride 528B: offsets mod 128 step by 16B -> conflict-free ldmatrix.
// ---------------------------------------------------------------------------
#define LS_RS     528                      // bytes per 256-fp16 SMEM row (+16)
#define LS_ABYTES (64 * LS_RS)             // 33792
#define LS_BBYTES (128 * LS_RS)            // 67584
#define LS_STAGE  (LS_ABYTES + LS_BBYTES)  // 101376
#define LS_CHUNKS 4
#define LS_SMEM   (2 * LS_STAGE)           // 202752 (z-tile aliases this)

__global__ __launch_bounds__(512, 1) void lstm_mma_step_kernel(
    const int* __restrict__ tokens, int t)
{
    extern __shared__ char smem[];
    const unsigned sb = smem_to_u32(smem);
    float (*zs)[132] = reinterpret_cast<float (*)[132]>(smem);  // 64x132 fp32
    __shared__ int toks[64];

    const int tid = threadIdx.x;
    const int wid = tid >> 5;
    const int lane = tid & 31;
    const int warp_m = wid >> 2;        // 0..3 (16 rows each)
    const int warp_n = wid & 3;         // 0..3 (32 cols each)
    const int c0  = blockIdx.x * 128;   // interleaved col base
    const int b0  = blockIdx.y * 64;
    const int dir = blockIdx.z;
    const int s  = dir ? (Sq - 1 - t) : t;
    const int sp = dir ? (Sq - t) : (t - 1);   // previous step's s (t>0)

    const __half* Uhi = dir ? g_Uhib : g_Uhif;

    if (tid < 64) toks[tid] = tokens[(b0 + tid) * Sq + s];

    float acc[4][4];                    // [nt][quad]
#pragma unroll
    for (int nt = 0; nt < 4; nt++)
#pragma unroll
        for (int q = 0; q < 4; q++) acc[nt][q] = 0.f;

    if (t > 0) {
        auto issue_chunk = [&](int kc, int buf) {
            const unsigned bb = sb + buf * LS_STAGE;
#pragma unroll
            for (int i = 0; i < 12; i++) {
                int id = i * 512 + tid;            // 0..6143
                if (id < 2048) {
                    int r = id >> 5, ch = id & 31; // A: 64 rows x 32 chunks
                    unsigned dst = bb + r * LS_RS + ch * 16;
                    cp_async16(dst, g_Ahi +
                        ((size_t)(b0 + r) * Sq + sp) * Kout + dir * Hq + kc + ch * 8);
                } else {
                    int id2 = id - 2048;           // 0..4095: U, 128 rows x 32
                    int r = id2 >> 5, ch = id2 & 31;
                    unsigned dst = bb + LS_ABYTES + r * LS_RS + ch * 16;
                    cp_async16(dst, Uhi + (size_t)(c0 + r) * Hq + kc + ch * 8);
                }
            }
            CP_COMMIT();
        };

        issue_chunk(0, 0);
        issue_chunk(256, 1);

        for (int c = 0; c < LS_CHUNKS; c++) {
            if (c < LS_CHUNKS - 1) { CP_WAIT(1); } else { CP_WAIT(0); }
            __syncthreads();

            const unsigned bb  = sb + (c & 1) * LS_STAGE;
            const unsigned sAh = bb;
            const unsigned sBh = bb + LS_ABYTES;

#pragma unroll
            for (int kh = 0; kh < 16; kh++) {
                const int koff = kh * 32;          // bytes (16 fp16)
                const unsigned a_off =
                    (warp_m * 16 + (lane & 15)) * LS_RS + koff + ((lane >> 4) << 4);
                const unsigned b_off =
                    (warp_n * 32 + (lane & 7) + ((lane >> 4) << 3)) * LS_RS +
                    koff + (((lane >> 3) & 1) << 4);

                unsigned aH[4], bH[4][2];
                ldmatrix_x4(aH, sAh + a_off);
#pragma unroll
                for (int np = 0; np < 2; np++) {
                    unsigned r4[4];
                    ldmatrix_x4(r4, sBh + b_off + np * 16 * LS_RS);
                    bH[np * 2][0] = r4[0]; bH[np * 2][1] = r4[1];
                    bH[np * 2 + 1][0] = r4[2]; bH[np * 2 + 1][1] = r4[3];
                }

#pragma unroll
                for (int nt = 0; nt < 4; nt++)
                    mma_f16(acc[nt], aH, bH[nt]);
            }

            __syncthreads();
            if (c + 2 < LS_CHUNKS) issue_chunk((c + 2) * 256, c & 1);
        }
    }

    __syncthreads();   // all MMA reads done; safe to alias stage smem as zs

    // fragments -> z tile
    {
        int r = warp_m * 16 + (lane >> 2);
#pragma unroll
        for (int nt = 0; nt < 4; nt++) {
            int col = warp_n * 32 + nt * 8 + 2 * (lane & 3);
            *reinterpret_cast<float2*>(&zs[r][col]) =
                make_float2(acc[nt][0], acc[nt][1]);
            *reinterpret_cast<float2*>(&zs[r + 8][col]) =
                make_float2(acc[nt][2], acc[nt][3]);
        }
    }
    __syncthreads();

    // fused gate update: 64 rows x 32 hidden units = 2048 items / 512 threads
    const float* embW = dir ? g_embWtb : g_embWtf;
    float* cptr = &g_c[dir][0];
    const int j0q = c0 >> 2;

#pragma unroll
    for (int it = 0; it < 4; it++) {
        int idx = it * 512 + tid;
        int r  = idx >> 5;     // 0..63
        int jj = idx & 31;     // 0..31
        int j = j0q + jj;

        float4 z4 = *reinterpret_cast<const float4*>(&zs[r][jj * 4]);
        int tok = toks[r];
        float4 ew = *reinterpret_cast<const float4*>(
            &embW[(size_t)tok * G4H + (j << 2)]);
        float zi = z4.x + ew.x;
        float zf = z4.y + ew.y;
        float zg = z4.z + ew.z;
        float zo = z4.w + ew.w;

        float ig = sigmoidf_fast(zi);
        float fg = sigmoidf_fast(zf);
        float og = sigmoidf_fast(zo);
        float gg = dir ? fmaxf(zg, 0.f) : tanhf(zg);

        int ci = (b0 + r) * Hq + j;
        float cv = fg * cptr[ci] + ig * gg;
        cptr[ci] = cv;
        float hc = dir ? fmaxf(cv, 0.f) : tanhf(cv);
        float hv = og * hc;

        size_t ao = ((size_t)(b0 + r) * Sq + s) * Kout + dir * Hq + j;
        g_Ahi[ao] = __float2half(hv);
    }
}

// ---------------------------------------------------------------------------
// Launch
// ---------------------------------------------------------------------------
extern "C" void kernel_launch(void* const* d_in, const int* in_sizes, int n_in,
                              void* d_out, int out_size) {
    (void)in_sizes; (void)n_in; (void)out_size;
    const int*   tokens = (const int*)  d_in[0];
    const float* emb    = (const float*)d_in[1];
    const float* Wf     = (const float*)d_in[2];
    const float* Uf     = (const float*)d_in[3];
    const float* bf     = (const float*)d_in[4];
    const float* Wb     = (const float*)d_in[5];
    const float* Ub     = (const float*)d_in[6];
    const float* bb     = (const float*)d_in[7];
    const float* Wd     = (const float*)d_in[8];
    const float* bd     = (const float*)d_in[9];
    float* out = (float*)d_out;

    float *p_btf, *p_btb, *p_embWtf, *p_embWtb;
    __half *p_emb16, *p_Wt16f, *p_Wt16b, *p_Ahi, *p_Bhi;
    cudaGetSymbolAddress((void**)&p_btf,    g_btf);
    cudaGetSymbolAddress((void**)&p_btb,    g_btb);
    cudaGetSymbolAddress((void**)&p_embWtf, g_embWtf);
    cudaGetSymbolAddress((void**)&p_embWtb, g_embWtb);
    cudaGetSymbolAddress((void**)&p_emb16,  g_emb16);
    cudaGetSymbolAddress((void**)&p_Wt16f,  g_Wt16f);
    cudaGetSymbolAddress((void**)&p_Wt16b,  g_Wt16b);
    cudaGetSymbolAddress((void**)&p_Ahi,    g_Ahi);
    cudaGetSymbolAddress((void**)&p_Bhi,    g_Bhi);

    cudaFuncSetAttribute(hgemm_bias_kernel,
                         cudaFuncAttributeMaxDynamicSharedMemorySize, OG_SMEM);
    cudaFuncSetAttribute(lstm_mma_step_kernel,
                         cudaFuncAttributeMaxDynamicSharedMemorySize, LS_SMEM);

    init_state_kernel<<<(Vq * Eq + 255) / 256, 256>>>(emb);
    interleave_b_kernel<<<(G4H + 255) / 256, 256>>>(bf, bb);
    transpose_W16_kernel<<<dim3(Hq / 32, Eq / 32, 8), dim3(32, 8)>>>(Wf, Wb);
    split_transpose_U_kernel<<<dim3(Hq / 32, Hq / 32, 8), dim3(32, 8)>>>(Uf, Ub);
    split_transpose_Wd_kernel<<<dim3(Vq / 32, Kout / 32), dim3(32, 8)>>>(Wd);

    // embWt = emb16 @ Wt16^T + bt  (gate-interleaved, bias folded), fp16 HMMA
    hgemm_bias_kernel<<<dim3(G4H / 128, Vq / 128), 256, OG_SMEM>>>(
        p_emb16, p_Wt16f, p_btf, p_embWtf, Eq, G4H);
    hgemm_bias_kernel<<<dim3(G4H / 128, Vq / 128), 256, OG_SMEM>>>(
        p_emb16, p_Wt16b, p_btb, p_embWtb, Eq, G4H);

    // 256 sequential recurrent steps (both directions per launch), HMMA fp16
    for (int t = 0; t < Sq; t++) {
        lstm_mma_step_kernel<<<dim3(G4H / 128, Bq / 64, 2), 512, LS_SMEM>>>(
            tokens, t);
    }

    // out = hcat16 @ Wd16^T + bd
    hgemm_bias_kernel<<<dim3(Vq / 128, Mout / 128), 256, OG_SMEM>>>(
        p_Ahi, p_Bhi, bd, out, Kout, Vq);
}

// round 15
// speedup vs baseline: 3.6894x; 1.0444x over previous
#include <cuda_runtime.h>
#include <cuda_fp16.h>
#include <math.h>

// Problem dims
#define Bq   128
#define Sq   256
#define Eq   512
#define Hq   1024
#define Vq   2048
#define G4H  4096   // 4*H
#define Kout 2048   // 2*H (output GEMM K)
#define Mout (Bq * Sq)

// ---------------------------------------------------------------------------
// Scratch (device globals; no allocation allowed)
// ---------------------------------------------------------------------------
__device__ float g_btf[G4H];
__device__ float g_btb[G4H];
__device__ float g_embWtf[Vq * G4H];         // 32 MB (bias folded)
__device__ float g_embWtb[Vq * G4H];
__device__ float g_c[2][Bq * Hq];            // [dir] cell state (fp32)
__device__ unsigned g_barrier[4];            // per-(b-half, dir) step counters
__device__ __half g_emb16[Vq * Eq];          // 2 MB: emb in fp16
// W fp16, gate-interleaved, TRANSPOSED: [c=j*4+g][e]
__device__ __half g_Wt16f[G4H * Eq];         // 4 MB
__device__ __half g_Wt16b[G4H * Eq];
// Recurrent weights, plain fp16, gate-interleaved, TRANSPOSED: [n=j*4+g][k]
__device__ __half g_Uhif[G4H * Hq];          // 8 MB
__device__ __half g_Uhib[G4H * Hq];
// hcat fp16; row m = b*S+s, col = dir*H+j. A operand of the next recurrent
// step (rows at s_prev, via cp.async.cg = L2-direct) and of the output GEMM.
__device__ __half g_Ahi[(size_t)Mout * Kout]; // 128 MB
// Wd transposed, plain fp16: B[n][k] = Wd[k][n]
__device__ __half g_Bhi[Vq * Kout];          // 8 MB

// ---------------------------------------------------------------------------
// Small helpers
// ---------------------------------------------------------------------------
__device__ __forceinline__ float sigmoidf_fast(float x) {
    return __fdividef(1.f, 1.f + __expf(-x));
}
__device__ __forceinline__ unsigned smem_to_u32(const void* p) {
    unsigned a;
    asm("{ .reg .u64 t; cvta.to.shared.u64 t, %1; cvt.u32.u64 %0, t; }"
        : "=r"(a) : "l"(p));
    return a;
}
// Release-arrive / acquire-peek (no CCTL.IVALL, no full membar)
__device__ __forceinline__ void bar_arrive_release(unsigned* p) {
    unsigned old;
    asm volatile("atom.release.gpu.global.add.u32 %0, [%1], 1;"
                 : "=r"(old) : "l"(p) : "memory");
}
__device__ __forceinline__ unsigned bar_peek_acquire(const unsigned* p) {
    unsigned v;
    asm volatile("ld.acquire.gpu.global.u32 %0, [%1];"
                 : "=r"(v) : "l"(p) : "memory");
    return v;
}

// ---------------------------------------------------------------------------
// sm_80+ portable async-copy + ldmatrix + HMMA (fp16, fp32 accumulate)
// ---------------------------------------------------------------------------
__device__ __forceinline__ void cp_async16(unsigned smem_addr, const void* gptr) {
    asm volatile("cp.async.cg.shared.global [%0], [%1], 16;"
                 :: "r"(smem_addr), "l"(gptr));
}
#define CP_COMMIT() asm volatile("cp.async.commit_group;" ::: "memory")
#define CP_WAIT(n)  asm volatile("cp.async.wait_group %0;" :: "n"(n) : "memory")

__device__ __forceinline__ void ldmatrix_x4(unsigned* r, unsigned addr) {
    asm volatile("ldmatrix.sync.aligned.m8n8.x4.shared.b16 {%0,%1,%2,%3}, [%4];"
                 : "=r"(r[0]), "=r"(r[1]), "=r"(r[2]), "=r"(r[3]) : "r"(addr));
}
__device__ __forceinline__ void mma_f16(float* c, const unsigned* a,
                                        const unsigned* b) {
    asm volatile(
        "mma.sync.aligned.m16n8k16.row.col.f32.f16.f16.f32 "
        "{%0,%1,%2,%3}, {%4,%5,%6,%7}, {%8,%9}, {%0,%1,%2,%3};"
        : "+f"(c[0]), "+f"(c[1]), "+f"(c[2]), "+f"(c[3])
        : "r"(a[0]), "r"(a[1]), "r"(a[2]), "r"(a[3]), "r"(b[0]), "r"(b[1]));
}

// ---------------------------------------------------------------------------
// Zero the cell state + step barriers + fp16 emb conversion
// ---------------------------------------------------------------------------
__global__ void init_state_kernel(const float* __restrict__ emb) {
    int i = blockIdx.x * blockDim.x + threadIdx.x;
    if (i < Bq * Hq) { g_c[0][i] = 0.f; g_c[1][i] = 0.f; }
    if (i < 4) g_barrier[i] = 0u;
    if (i < Vq * Eq) g_emb16[i] = __float2half(emb[i]);
}

// ---------------------------------------------------------------------------
// Gate-interleave biases:  bt[j*4+g] = b[g*H+j]
// ---------------------------------------------------------------------------
__global__ void interleave_b_kernel(const float* __restrict__ bf,
                                    const float* __restrict__ bb) {
    int idx = blockIdx.x * blockDim.x + threadIdx.x;
    if (idx < G4H) {
        int src = (idx & 3) * Hq + (idx >> 2);
        g_btf[idx] = bf[src];
        g_btb[idx] = bb[src];
    }
}

// ---------------------------------------------------------------------------
// fp16 + transpose + gate-interleave W:  Wt16[dir][(j*4+g)][e] = fp16(W[e][g*H+j])
// ---------------------------------------------------------------------------
__global__ void transpose_W16_kernel(const float* __restrict__ Wf,
                                     const float* __restrict__ Wb) {
    __shared__ float ts[32][33];
    int j0 = blockIdx.x * 32;
    int e0 = blockIdx.y * 32;
    int g   = blockIdx.z & 3;
    int dir = blockIdx.z >> 2;
    const float* W = dir ? Wb : Wf;
    __half* D = dir ? g_Wt16b : g_Wt16f;
    int tx = threadIdx.x, ty = threadIdx.y;
#pragma unroll
    for (int i = 0; i < 32; i += 8)
        ts[ty + i][tx] = W[(size_t)(e0 + ty + i) * G4H + g * Hq + j0 + tx];
    __syncthreads();
#pragma unroll
    for (int i = 0; i < 32; i += 8) {
        int j = j0 + ty + i;
        float v = ts[tx][ty + i];          // W[e0+tx][g*H + j]
        size_t o = (size_t)((j << 2) + g) * Eq + e0 + tx;
        D[o] = __float2half(v);
    }
}

// ---------------------------------------------------------------------------
// fp16 + transpose + gate-interleave U:  U16[dir][(j*4+g)][k] = fp16(U[k][g*H+j])
// ---------------------------------------------------------------------------
__global__ void split_transpose_U_kernel(const float* __restrict__ Uf,
                                         const float* __restrict__ Ub) {
    __shared__ float ts[32][33];
    int j0 = blockIdx.x * 32;
    int k0 = blockIdx.y * 32;
    int g   = blockIdx.z & 3;
    int dir = blockIdx.z >> 2;
    const float* U = dir ? Ub : Uf;
    __half* Dhi = dir ? g_Uhib : g_Uhif;
    int tx = threadIdx.x, ty = threadIdx.y;
#pragma unroll
    for (int i = 0; i < 32; i += 8)
        ts[ty + i][tx] = U[(size_t)(k0 + ty + i) * G4H + g * Hq + j0 + tx];
    __syncthreads();
#pragma unroll
    for (int i = 0; i < 32; i += 8) {
        int j = j0 + ty + i;
        float v = ts[tx][ty + i];          // U[k0+tx][g*H + j]
        size_t o = (size_t)((j << 2) + g) * Hq + k0 + tx;
        Dhi[o] = __float2half(v);
    }
}

// ---------------------------------------------------------------------------
// fp16 + transpose Wd:  Bhi[n][k] = fp16(Wd[k][n])
// ---------------------------------------------------------------------------
__global__ void split_transpose_Wd_kernel(const float* __restrict__ Wd) {
    __shared__ float ts[32][33];
    int n0 = blockIdx.x * 32;
    int k0 = blockIdx.y * 32;
    int tx = threadIdx.x, ty = threadIdx.y;
#pragma unroll
    for (int i = 0; i < 32; i += 8)
        ts[ty + i][tx] = Wd[(size_t)(k0 + ty + i) * Vq + n0 + tx];
    __syncthreads();
#pragma unroll
    for (int i = 0; i < 32; i += 8) {
        float v = ts[tx][ty + i];            // Wd[k0+tx][n0+ty+i]
        size_t o = (size_t)(n0 + ty + i) * Kout + k0 + tx;
        g_Bhi[o] = __float2half(v);
    }
}

// ---------------------------------------------------------------------------
// Generic fp16 HMMA GEMM with fp32 bias + fp32 output (unchanged from R13):
//   out[m][n] = A16[m][:] . B16[n][:] + bias[n]
// ---------------------------------------------------------------------------
#define OG_BK       64
#define OG_RS       144
#define OG_TILE_B   (128 * OG_RS)       // 18432
#define OG_STAGE_B  (2 * OG_TILE_B)
#define OG_SMEM     (2 * OG_STAGE_B)    // 73728

__global__ __launch_bounds__(256, 2) void hgemm_bias_kernel(
    const __half* __restrict__ A, const __half* __restrict__ B,
    const float* __restrict__ bias, float* __restrict__ out,
    int K, int ldout)
{
    extern __shared__ char smem[];
    const unsigned sb = smem_to_u32(smem);
    const int tid = threadIdx.x;
    const int wid = tid >> 5;
    const int lane = tid & 31;
    const int warp_m = wid >> 2;
    const int warp_n = wid & 3;
    const int n0 = blockIdx.x * 128;
    const int m0 = blockIdx.y * 128;
    const int chunks = K >> 6;

    const __half* srcs[2] = {A, B};
    const int rowbase[2] = {m0, n0};

    auto issue_chunk = [&](int kc, int buf) {
        const unsigned bb = sb + buf * OG_STAGE_B;
#pragma unroll
        for (int i = 0; i < 8; i++) {
            int id   = i * 256 + tid;
            int tile = id >> 10;
            int rem  = id & 1023;
            int r    = rem >> 3;
            int ch   = rem & 7;
            unsigned dst = bb + tile * OG_TILE_B + r * OG_RS + ch * 16;
            const void* g = srcs[tile] +
                            (size_t)(rowbase[tile] + r) * K + kc + ch * 8;
            cp_async16(dst, g);
        }
        CP_COMMIT();
    };

    float acc[4][4][4];
#pragma unroll
    for (int mt = 0; mt < 4; mt++)
#pragma unroll
        for (int nt = 0; nt < 4; nt++)
#pragma unroll
            for (int q = 0; q < 4; q++) acc[mt][nt][q] = 0.f;

    issue_chunk(0, 0);
    issue_chunk(OG_BK, 1);

    for (int c = 0; c < chunks; c++) {
        if (c < chunks - 1) { CP_WAIT(1); } else { CP_WAIT(0); }
        __syncthreads();

        const unsigned bb  = sb + (c & 1) * OG_STAGE_B;
        const unsigned sAh = bb;
        const unsigned sBh = bb + OG_TILE_B;

#pragma unroll
        for (int kh = 0; kh < 4; kh++) {
            const int koff = kh * 32;
            const unsigned a_off =
                (warp_m * 64 + (lane & 15)) * OG_RS + koff + ((lane >> 4) << 4);
            const unsigned b_off =
                (warp_n * 32 + (lane & 7) + ((lane >> 4) << 3)) * OG_RS +
                koff + (((lane >> 3) & 1) << 4);

            unsigned aH[4][4], bH[4][2];
#pragma unroll
            for (int mt = 0; mt < 4; mt++)
                ldmatrix_x4(aH[mt], sAh + a_off + mt * 16 * OG_RS);
#pragma unroll
            for (int np = 0; np < 2; np++) {
                unsigned r4[4];
                ldmatrix_x4(r4, sBh + b_off + np * 16 * OG_RS);
                bH[np * 2][0] = r4[0]; bH[np * 2][1] = r4[1];
                bH[np * 2 + 1][0] = r4[2]; bH[np * 2 + 1][1] = r4[3];
            }

#pragma unroll
            for (int mt = 0; mt < 4; mt++)
#pragma unroll
                for (int nt = 0; nt < 4; nt++)
                    mma_f16(acc[mt][nt], aH[mt], bH[nt]);
        }

        __syncthreads();
        if (c + 2 < chunks) issue_chunk((c + 2) * OG_BK, c & 1);
    }

#pragma unroll
    for (int mt = 0; mt < 4; mt++) {
        int r0 = m0 + warp_m * 64 + mt * 16 + (lane >> 2);
#pragma unroll
        for (int nt = 0; nt < 4; nt++) {
            int col = n0 + warp_n * 32 + nt * 8 + 2 * (lane & 3);
            float b0v = bias[col], b1v = bias[col + 1];
            float2 v0 = make_float2(acc[mt][nt][0] + b0v, acc[mt][nt][1] + b1v);
            float2 v1 = make_float2(acc[mt][nt][2] + b0v, acc[mt][nt][3] + b1v);
            *reinterpret_cast<float2*>(out + (size_t)r0 * ldout + col) = v0;
            *reinterpret_cast<float2*>(out + (size_t)(r0 + 8) * ldout + col) = v1;
        }
    }
}

// ---------------------------------------------------------------------------
// PERSISTENT recurrence: all 256 steps in ONE launch (step body = R13).
// Grid (32, 2, 2) = 128 CTAs, 512 threads, 203KB smem -> 1 CTA/SM, all
// wave-1 resident. CTA (x,y,z) produces h rows [64y,64y+64) cols [32x,32x+32)
// of dir z and consumes rows [64y,64y+64) ALL cols of dir z -> sync group
// (y,z): four independent 32-CTA barriers.
// Cross-CTA data (g_Ahi) is read ONLY via cp.async.cg (L2-direct), so a
// release-atomic arrive + acquire-load spin by tid0 suffices — no
// __threadfence, no L1 flush (the R8 poison).
// ---------------------------------------------------------------------------
#define LS_RS     528                      // bytes per 256-fp16 SMEM row (+16)
#define LS_ABYTES (64 * LS_RS)             // 33792
#define LS_BBYTES (128 * LS_RS)            // 67584
#define LS_STAGE  (LS_ABYTES + LS_BBYTES)  // 101376
#define LS_CHUNKS 4
#define LS_SMEM   (2 * LS_STAGE)           // 202752 (z-tile aliases this)

__global__ __launch_bounds__(512, 1) void lstm_persistent_kernel(
    const int* __restrict__ tokens)
{
    extern __shared__ char smem[];
    const unsigned sb = smem_to_u32(smem);
    float (*zs)[132] = reinterpret_cast<float (*)[132]>(smem);  // 64x132 fp32
    __shared__ int toks[64];

    const int tid = threadIdx.x;
    const int wid = tid >> 5;
    const int lane = tid & 31;
    const int warp_m = wid >> 2;        // 0..3 (16 rows each)
    const int warp_n = wid & 3;         // 0..3 (32 cols each)
    const int c0  = blockIdx.x * 128;   // interleaved col base
    const int b0  = blockIdx.y * 64;
    const int dir = blockIdx.z;
    const int gid = blockIdx.y * 2 + blockIdx.z;

    const __half* Uhi = dir ? g_Uhib : g_Uhif;
    const float* embW = dir ? g_embWtb : g_embWtf;
    float* cptr = &g_c[dir][0];
    const int j0q = c0 >> 2;

    for (int t = 0; t < Sq; t++) {
        const int s  = dir ? (Sq - 1 - t) : t;
        const int sp = dir ? (Sq - t) : (t - 1);   // previous step's s (t>0)

        if (tid < 64) toks[tid] = tokens[(b0 + tid) * Sq + s];

        float acc[4][4];                    // [nt][quad]
#pragma unroll
        for (int nt = 0; nt < 4; nt++)
#pragma unroll
            for (int q = 0; q < 4; q++) acc[nt][q] = 0.f;

        if (t > 0) {
            auto issue_chunk = [&](int kc, int buf) {
                const unsigned bb = sb + buf * LS_STAGE;
#pragma unroll
                for (int i = 0; i < 12; i++) {
                    int id = i * 512 + tid;            // 0..6143
                    if (id < 2048) {
                        int r = id >> 5, ch = id & 31; // A: 64 rows x 32
                        unsigned dst = bb + r * LS_RS + ch * 16;
                        cp_async16(dst, g_Ahi +
                            ((size_t)(b0 + r) * Sq + sp) * Kout + dir * Hq + kc + ch * 8);
                    } else {
                        int id2 = id - 2048;           // U: 128 rows x 32
                        int r = id2 >> 5, ch = id2 & 31;
                        unsigned dst = bb + LS_ABYTES + r * LS_RS + ch * 16;
                        cp_async16(dst, Uhi + (size_t)(c0 + r) * Hq + kc + ch * 8);
                    }
                }
                CP_COMMIT();
            };

            issue_chunk(0, 0);
            issue_chunk(256, 1);

            for (int c = 0; c < LS_CHUNKS; c++) {
                if (c < LS_CHUNKS - 1) { CP_WAIT(1); } else { CP_WAIT(0); }
                __syncthreads();

                const unsigned bb  = sb + (c & 1) * LS_STAGE;
                const unsigned sAh = bb;
                const unsigned sBh = bb + LS_ABYTES;

#pragma unroll
                for (int kh = 0; kh < 16; kh++) {
                    const int koff = kh * 32;          // bytes (16 fp16)
                    const unsigned a_off =
                        (warp_m * 16 + (lane & 15)) * LS_RS + koff + ((lane >> 4) << 4);
                    const unsigned b_off =
                        (warp_n * 32 + (lane & 7) + ((lane >> 4) << 3)) * LS_RS +
                        koff + (((lane >> 3) & 1) << 4);

                    unsigned aH[4], bH[4][2];
                    ldmatrix_x4(aH, sAh + a_off);
#pragma unroll
                    for (int np = 0; np < 2; np++) {
                        unsigned r4[4];
                        ldmatrix_x4(r4, sBh + b_off + np * 16 * LS_RS);
                        bH[np * 2][0] = r4[0]; bH[np * 2][1] = r4[1];
                        bH[np * 2 + 1][0] = r4[2]; bH[np * 2 + 1][1] = r4[3];
                    }

#pragma unroll
                    for (int nt = 0; nt < 4; nt++)
                        mma_f16(acc[nt], aH, bH[nt]);
                }

                __syncthreads();
                if (c + 2 < LS_CHUNKS) issue_chunk((c + 2) * 256, c & 1);
            }
        }

        __syncthreads();   // all MMA reads done; safe to alias stage smem as zs

        // fragments -> z tile
        {
            int r = warp_m * 16 + (lane >> 2);
#pragma unroll
            for (int nt = 0; nt < 4; nt++) {
                int col = warp_n * 32 + nt * 8 + 2 * (lane & 3);
                *reinterpret_cast<float2*>(&zs[r][col]) =
                    make_float2(acc[nt][0], acc[nt][1]);
                *reinterpret_cast<float2*>(&zs[r + 8][col]) =
                    make_float2(acc[nt][2], acc[nt][3]);
            }
        }
        __syncthreads();

        // fused gate update: 64 rows x 32 hidden units / 512 threads
#pragma unroll
        for (int it = 0; it < 4; it++) {
            int idx = it * 512 + tid;
            int r  = idx >> 5;     // 0..63
            int jj = idx & 31;     // 0..31
            int j = j0q + jj;

            float4 z4 = *reinterpret_cast<const float4*>(&zs[r][jj * 4]);
            int tok = toks[r];
            float4 ew = *reinterpret_cast<const float4*>(
                &embW[(size_t)tok * G4H + (j << 2)]);
            float zi = z4.x + ew.x;
            float zf = z4.y + ew.y;
            float zg = z4.z + ew.z;
            float zo = z4.w + ew.w;

            float ig = sigmoidf_fast(zi);
            float fg = sigmoidf_fast(zf);
            float og = sigmoidf_fast(zo);
            float gg = dir ? fmaxf(zg, 0.f) : tanhf(zg);

            int ci = (b0 + r) * Hq + j;
            float cv = fg * cptr[ci] + ig * gg;
            cptr[ci] = cv;
            float hc = dir ? fmaxf(cv, 0.f) : tanhf(cv);
            float hv = og * hc;

            size_t ao = ((size_t)(b0 + r) * Sq + s) * Kout + dir * Hq + j;
            g_Ahi[ao] = __float2half(hv);
        }

        // ---- 32-CTA group barrier (release/acquire, tid0 only) ----
        if (t + 1 < Sq) {
            __syncthreads();               // all epilogue STGs issued
            if (tid == 0) {
                bar_arrive_release(&g_barrier[gid]);
                unsigned tgt = 32u * (unsigned)(t + 1);
                while (bar_peek_acquire(&g_barrier[gid]) < tgt) {}
            }
            __syncthreads();               // broadcast acquire to all threads
        }
    }
}

// ---------------------------------------------------------------------------
// Launch
// ---------------------------------------------------------------------------
extern "C" void kernel_launch(void* const* d_in, const int* in_sizes, int n_in,
                              void* d_out, int out_size) {
    (void)in_sizes; (void)n_in; (void)out_size;
    const int*   tokens = (const int*)  d_in[0];
    const float* emb    = (const float*)d_in[1];
    const float* Wf     = (const float*)d_in[2];
    const float* Uf     = (const float*)d_in[3];
    const float* bf     = (const float*)d_in[4];
    const float* Wb     = (const float*)d_in[5];
    const float* Ub     = (const float*)d_in[6];
    const float* bb     = (const float*)d_in[7];
    const float* Wd     = (const float*)d_in[8];
    const float* bd     = (const float*)d_in[9];
    float* out = (float*)d_out;

    float *p_btf, *p_btb, *p_embWtf, *p_embWtb;
    __half *p_emb16, *p_Wt16f, *p_Wt16b, *p_Ahi, *p_Bhi;
    cudaGetSymbolAddress((void**)&p_btf,    g_btf);
    cudaGetSymbolAddress((void**)&p_btb,    g_btb);
    cudaGetSymbolAddress((void**)&p_embWtf, g_embWtf);
    cudaGetSymbolAddress((void**)&p_embWtb, g_embWtb);
    cudaGetSymbolAddress((void**)&p_emb16,  g_emb16);
    cudaGetSymbolAddress((void**)&p_Wt16f,  g_Wt16f);
    cudaGetSymbolAddress((void**)&p_Wt16b,  g_Wt16b);
    cudaGetSymbolAddress((void**)&p_Ahi,    g_Ahi);
    cudaGetSymbolAddress((void**)&p_Bhi,    g_Bhi);

    cudaFuncSetAttribute(hgemm_bias_kernel,
                         cudaFuncAttributeMaxDynamicSharedMemorySize, OG_SMEM);
    cudaFuncSetAttribute(lstm_persistent_kernel,
                         cudaFuncAttributeMaxDynamicSharedMemorySize, LS_SMEM);

    init_state_kernel<<<(Vq * Eq + 255) / 256, 256>>>(emb);
    interleave_b_kernel<<<(G4H + 255) / 256, 256>>>(bf, bb);
    transpose_W16_kernel<<<dim3(Hq / 32, Eq / 32, 8), dim3(32, 8)>>>(Wf, Wb);
    split_transpose_U_kernel<<<dim3(Hq / 32, Hq / 32, 8), dim3(32, 8)>>>(Uf, Ub);
    split_transpose_Wd_kernel<<<dim3(Vq / 32, Kout / 32), dim3(32, 8)>>>(Wd);

    // embWt = emb16 @ Wt16^T + bt  (gate-interleaved, bias folded), fp16 HMMA
    hgemm_bias_kernel<<<dim3(G4H / 128, Vq / 128), 256, OG_SMEM>>>(
        p_emb16, p_Wt16f, p_btf, p_embWtf, Eq, G4H);
    hgemm_bias_kernel<<<dim3(G4H / 128, Vq / 128), 256, OG_SMEM>>>(
        p_emb16, p_Wt16b, p_btb, p_embWtb, Eq, G4H);

    // ALL 256 recurrent steps in one persistent launch
    lstm_persistent_kernel<<<dim3(G4H / 128, Bq / 64, 2), 512, LS_SMEM>>>(tokens);

    // out = hcat16 @ Wd16^T + bd
    hgemm_bias_kernel<<<dim3(Vq / 128, Mout / 128), 256, OG_SMEM>>>(
        p_Ahi, p_Bhi, bd, out, Kout, Vq);
}

// round 16
// speedup vs baseline: 4.2013x; 1.1388x over previous
#include <cuda_runtime.h>
#include <cuda_fp16.h>
#include <math.h>

// Problem dims
#define Bq   128
#define Sq   256
#define Eq   512
#define Hq   1024
#define Vq   2048
#define G4H  4096   // 4*H
#define Kout 2048   // 2*H (output GEMM K)
#define Mout (Bq * Sq)

// ---------------------------------------------------------------------------
// Scratch (device globals; no allocation allowed)
// ---------------------------------------------------------------------------
__device__ float g_btf[G4H];
__device__ float g_btb[G4H];
__device__ float g_embWtf[Vq * G4H];         // 32 MB (bias folded)
__device__ float g_embWtb[Vq * G4H];
__device__ float g_c[2][Bq * Hq];            // [dir] cell state (fp32)
__device__ unsigned g_barrier[4];            // per-(b-half, dir) step counters
__device__ __half g_emb16[Vq * Eq];          // 2 MB: emb in fp16
// W fp16, gate-interleaved, TRANSPOSED: [c=j*4+g][e]
__device__ __half g_Wt16f[G4H * Eq];         // 4 MB
__device__ __half g_Wt16b[G4H * Eq];
// Recurrent weights, plain fp16, gate-interleaved, TRANSPOSED: [n=j*4+g][k]
__device__ __half g_Uhif[G4H * Hq];          // 8 MB
__device__ __half g_Uhib[G4H * Hq];
// hcat fp16; row m = b*S+s, col = dir*H+j.
__device__ __half g_Ahi[(size_t)Mout * Kout]; // 128 MB
// Wd transposed, plain fp16: B[n][k] = Wd[k][n]
__device__ __half g_Bhi[Vq * Kout];          // 8 MB

// ---------------------------------------------------------------------------
// Small helpers
// ---------------------------------------------------------------------------
__device__ __forceinline__ float sigmoidf_fast(float x) {
    return __fdividef(1.f, 1.f + __expf(-x));
}
__device__ __forceinline__ unsigned smem_to_u32(const void* p) {
    unsigned a;
    asm("{ .reg .u64 t; cvta.to.shared.u64 t, %1; cvt.u32.u64 %0, t; }"
        : "=r"(a) : "l"(p));
    return a;
}
__device__ __forceinline__ void bar_arrive_release(unsigned* p) {
    unsigned old;
    asm volatile("atom.release.gpu.global.add.u32 %0, [%1], 1;"
                 : "=r"(old) : "l"(p) : "memory");
}
__device__ __forceinline__ unsigned bar_peek_acquire(const unsigned* p) {
    unsigned v;
    asm volatile("ld.acquire.gpu.global.u32 %0, [%1];"
                 : "=r"(v) : "l"(p) : "memory");
    return v;
}

// ---------------------------------------------------------------------------
// sm_80+ portable async-copy + ldmatrix + HMMA (fp16, fp32 accumulate)
// ---------------------------------------------------------------------------
__device__ __forceinline__ void cp_async16(unsigned smem_addr, const void* gptr) {
    asm volatile("cp.async.cg.shared.global [%0], [%1], 16;"
                 :: "r"(smem_addr), "l"(gptr));
}
#define CP_COMMIT() asm volatile("cp.async.commit_group;" ::: "memory")
#define CP_WAIT(n)  asm volatile("cp.async.wait_group %0;" :: "n"(n) : "memory")

__device__ __forceinline__ void ldmatrix_x4(unsigned* r, unsigned addr) {
    asm volatile("ldmatrix.sync.aligned.m8n8.x4.shared.b16 {%0,%1,%2,%3}, [%4];"
                 : "=r"(r[0]), "=r"(r[1]), "=r"(r[2]), "=r"(r[3]) : "r"(addr));
}
__device__ __forceinline__ void mma_f16(float* c, const unsigned* a,
                                        const unsigned* b) {
    asm volatile(
        "mma.sync.aligned.m16n8k16.row.col.f32.f16.f16.f32 "
        "{%0,%1,%2,%3}, {%4,%5,%6,%7}, {%8,%9}, {%0,%1,%2,%3};"
        : "+f"(c[0]), "+f"(c[1]), "+f"(c[2]), "+f"(c[3])
        : "r"(a[0]), "r"(a[1]), "r"(a[2]), "r"(a[3]), "r"(b[0]), "r"(b[1]));
}

// ---------------------------------------------------------------------------
// Zero the cell state + step barriers + fp16 emb conversion
// ---------------------------------------------------------------------------
__global__ void init_state_kernel(const float* __restrict__ emb) {
    int i = blockIdx.x * blockDim.x + threadIdx.x;
    if (i < Bq * Hq) { g_c[0][i] = 0.f; g_c[1][i] = 0.f; }
    if (i < 4) g_barrier[i] = 0u;
    if (i < Vq * Eq) g_emb16[i] = __float2half(emb[i]);
}

// ---------------------------------------------------------------------------
// Gate-interleave biases:  bt[j*4+g] = b[g*H+j]
// ---------------------------------------------------------------------------
__global__ void interleave_b_kernel(const float* __restrict__ bf,
                                    const float* __restrict__ bb) {
    int idx = blockIdx.x * blockDim.x + threadIdx.x;
    if (idx < G4H) {
        int src = (idx & 3) * Hq + (idx >> 2);
        g_btf[idx] = bf[src];
        g_btb[idx] = bb[src];
    }
}

// ---------------------------------------------------------------------------
// fp16 + transpose + gate-interleave W:  Wt16[dir][(j*4+g)][e] = fp16(W[e][g*H+j])
// ---------------------------------------------------------------------------
__global__ void transpose_W16_kernel(const float* __restrict__ Wf,
                                     const float* __restrict__ Wb) {
    __shared__ float ts[32][33];
    int j0 = blockIdx.x * 32;
    int e0 = blockIdx.y * 32;
    int g   = blockIdx.z & 3;
    int dir = blockIdx.z >> 2;
    const float* W = dir ? Wb : Wf;
    __half* D = dir ? g_Wt16b : g_Wt16f;
    int tx = threadIdx.x, ty = threadIdx.y;
#pragma unroll
    for (int i = 0; i < 32; i += 8)
        ts[ty + i][tx] = W[(size_t)(e0 + ty + i) * G4H + g * Hq + j0 + tx];
    __syncthreads();
#pragma unroll
    for (int i = 0; i < 32; i += 8) {
        int j = j0 + ty + i;
        float v = ts[tx][ty + i];
        size_t o = (size_t)((j << 2) + g) * Eq + e0 + tx;
        D[o] = __float2half(v);
    }
}

// ---------------------------------------------------------------------------
// fp16 + transpose + gate-interleave U
// ---------------------------------------------------------------------------
__global__ void split_transpose_U_kernel(const float* __restrict__ Uf,
                                         const float* __restrict__ Ub) {
    __shared__ float ts[32][33];
    int j0 = blockIdx.x * 32;
    int k0 = blockIdx.y * 32;
    int g   = blockIdx.z & 3;
    int dir = blockIdx.z >> 2;
    const float* U = dir ? Ub : Uf;
    __half* Dhi = dir ? g_Uhib : g_Uhif;
    int tx = threadIdx.x, ty = threadIdx.y;
#pragma unroll
    for (int i = 0; i < 32; i += 8)
        ts[ty + i][tx] = U[(size_t)(k0 + ty + i) * G4H + g * Hq + j0 + tx];
    __syncthreads();
#pragma unroll
    for (int i = 0; i < 32; i += 8) {
        int j = j0 + ty + i;
        float v = ts[tx][ty + i];
        size_t o = (size_t)((j << 2) + g) * Hq + k0 + tx;
        Dhi[o] = __float2half(v);
    }
}

// ---------------------------------------------------------------------------
// fp16 + transpose Wd:  Bhi[n][k] = fp16(Wd[k][n])
// ---------------------------------------------------------------------------
__global__ void split_transpose_Wd_kernel(const float* __restrict__ Wd) {
    __shared__ float ts[32][33];
    int n0 = blockIdx.x * 32;
    int k0 = blockIdx.y * 32;
    int tx = threadIdx.x, ty = threadIdx.y;
#pragma unroll
    for (int i = 0; i < 32; i += 8)
        ts[ty + i][tx] = Wd[(size_t)(k0 + ty + i) * Vq + n0 + tx];
    __syncthreads();
#pragma unroll
    for (int i = 0; i < 32; i += 8) {
        float v = ts[tx][ty + i];
        size_t o = (size_t)(n0 + ty + i) * Kout + k0 + tx;
        g_Bhi[o] = __float2half(v);
    }
}

// ---------------------------------------------------------------------------
// Generic fp16 HMMA GEMM with fp32 bias + fp32 output (unchanged, validated)
// ---------------------------------------------------------------------------
#define OG_BK       64
#define OG_RS       144
#define OG_TILE_B   (128 * OG_RS)
#define OG_STAGE_B  (2 * OG_TILE_B)
#define OG_SMEM     (2 * OG_STAGE_B)    // 73728

__global__ __launch_bounds__(256, 2) void hgemm_bias_kernel(
    const __half* __restrict__ A, const __half* __restrict__ B,
    const float* __restrict__ bias, float* __restrict__ out,
    int K, int ldout)
{
    extern __shared__ char smem[];
    const unsigned sb = smem_to_u32(smem);
    const int tid = threadIdx.x;
    const int wid = tid >> 5;
    const int lane = tid & 31;
    const int warp_m = wid >> 2;
    const int warp_n = wid & 3;
    const int n0 = blockIdx.x * 128;
    const int m0 = blockIdx.y * 128;
    const int chunks = K >> 6;

    const __half* srcs[2] = {A, B};
    const int rowbase[2] = {m0, n0};

    auto issue_chunk = [&](int kc, int buf) {
        const unsigned bb = sb + buf * OG_STAGE_B;
#pragma unroll
        for (int i = 0; i < 8; i++) {
            int id   = i * 256 + tid;
            int tile = id >> 10;
            int rem  = id & 1023;
            int r    = rem >> 3;
            int ch   = rem & 7;
            unsigned dst = bb + tile * OG_TILE_B + r * OG_RS + ch * 16;
            const void* g = srcs[tile] +
                            (size_t)(rowbase[tile] + r) * K + kc + ch * 8;
            cp_async16(dst, g);
        }
        CP_COMMIT();
    };

    float acc[4][4][4];
#pragma unroll
    for (int mt = 0; mt < 4; mt++)
#pragma unroll
        for (int nt = 0; nt < 4; nt++)
#pragma unroll
            for (int q = 0; q < 4; q++) acc[mt][nt][q] = 0.f;

    issue_chunk(0, 0);
    issue_chunk(OG_BK, 1);

    for (int c = 0; c < chunks; c++) {
        if (c < chunks - 1) { CP_WAIT(1); } else { CP_WAIT(0); }
        __syncthreads();

        const unsigned bb  = sb + (c & 1) * OG_STAGE_B;
        const unsigned sAh = bb;
        const unsigned sBh = bb + OG_TILE_B;

#pragma unroll
        for (int kh = 0; kh < 4; kh++) {
            const int koff = kh * 32;
            const unsigned a_off =
                (warp_m * 64 + (lane & 15)) * OG_RS + koff + ((lane >> 4) << 4);
            const unsigned b_off =
                (warp_n * 32 + (lane & 7) + ((lane >> 4) << 3)) * OG_RS +
                koff + (((lane >> 3) & 1) << 4);

            unsigned aH[4][4], bH[4][2];
#pragma unroll
            for (int mt = 0; mt < 4; mt++)
                ldmatrix_x4(aH[mt], sAh + a_off + mt * 16 * OG_RS);
#pragma unroll
            for (int np = 0; np < 2; np++) {
                unsigned r4[4];
                ldmatrix_x4(r4, sBh + b_off + np * 16 * OG_RS);
                bH[np * 2][0] = r4[0]; bH[np * 2][1] = r4[1];
                bH[np * 2 + 1][0] = r4[2]; bH[np * 2 + 1][1] = r4[3];
            }

#pragma unroll
            for (int mt = 0; mt < 4; mt++)
#pragma unroll
                for (int nt = 0; nt < 4; nt++)
                    mma_f16(acc[mt][nt], aH[mt], bH[nt]);
        }

        __syncthreads();
        if (c + 2 < chunks) issue_chunk((c + 2) * OG_BK, c & 1);
    }

#pragma unroll
    for (int mt = 0; mt < 4; mt++) {
        int r0 = m0 + warp_m * 64 + mt * 16 + (lane >> 2);
#pragma unroll
        for (int nt = 0; nt < 4; nt++) {
            int col = n0 + warp_n * 32 + nt * 8 + 2 * (lane & 3);
            float b0v = bias[col], b1v = bias[col + 1];
            float2 v0 = make_float2(acc[mt][nt][0] + b0v, acc[mt][nt][1] + b1v);
            float2 v1 = make_float2(acc[mt][nt][2] + b0v, acc[mt][nt][3] + b1v);
            *reinterpret_cast<float2*>(out + (size_t)r0 * ldout + col) = v0;
            *reinterpret_cast<float2*>(out + (size_t)(r0 + 8) * ldout + col) = v1;
        }
    }
}

// ---------------------------------------------------------------------------
// PERSISTENT recurrence with RESIDENT U-HALF.
// BK=128, 8 chunks. U chunks 0-3 live in smem for the whole kernel (loaded
// once); U chunks 4-7 and all A chunks stream through a 2-stage buffer.
// XOR swizzle (col16 ^= row&7) replaces padding -> rows are exactly 256B.
// smem: [buf0: U|A][buf1: U|A][Upers x4] = 48+48+128 = 224 KB. zs aliases buf0.
// Grid (32,2,2) = 128 CTAs, 512 threads, 1 CTA/SM, all wave-1 resident.
// ---------------------------------------------------------------------------
#define LP_RS     256                      // bytes per 128-fp16 row (swizzled)
#define LP_UCH    (128 * LP_RS)            // 32768: U chunk (128 rows)
#define LP_ACH    (64 * LP_RS)             // 16384: A chunk (64 rows)
#define LP_STAGE  (LP_UCH + LP_ACH)        // 49152: [U][A]
#define LP_UPOFF  (2 * LP_STAGE)           // 98304
#define LP_SMEM   (LP_UPOFF + 4 * LP_UCH)  // 229376

__global__ __launch_bounds__(512, 1) void lstm_persistent_kernel(
    const int* __restrict__ tokens)
{
    extern __shared__ char smem[];
    const unsigned sb = smem_to_u32(smem);
    float (*zs)[132] = reinterpret_cast<float (*)[132]>(smem);  // 64x132 fp32
    __shared__ int toks[64];

    const int tid = threadIdx.x;
    const int wid = tid >> 5;
    const int lane = tid & 31;
    const int warp_m = wid >> 2;        // 0..3 (16 rows each)
    const int warp_n = wid & 3;         // 0..3 (32 cols each)
    const int c0  = blockIdx.x * 128;   // interleaved col base
    const int b0  = blockIdx.y * 64;
    const int dir = blockIdx.z;
    const int gid = blockIdx.y * 2 + blockIdx.z;

    const __half* Uhi = dir ? g_Uhib : g_Uhif;
    const float* embW = dir ? g_embWtb : g_embWtf;
    float* cptr = &g_c[dir][0];
    const int j0q = c0 >> 2;

    // U chunk loader (swizzled): 128 rows x 16 chunks of 16B
    auto issue_U = [&](int kc, unsigned ubase) {
#pragma unroll
        for (int i = 0; i < 4; i++) {
            int id = i * 512 + tid;            // 0..2047
            int r = id >> 4, ch = id & 15;
            unsigned dst = ubase + r * LP_RS + ((unsigned)(ch ^ (r & 7)) << 4);
            cp_async16(dst, Uhi + (size_t)(c0 + r) * Hq + kc + ch * 8);
        }
    };

    // Preload resident U chunks 0-3 (once)
    issue_U(0,   sb + LP_UPOFF);
    issue_U(128, sb + LP_UPOFF + LP_UCH);
    issue_U(256, sb + LP_UPOFF + 2 * LP_UCH);
    issue_U(384, sb + LP_UPOFF + 3 * LP_UCH);
    CP_COMMIT();
    CP_WAIT(0);
    __syncthreads();

    for (int t = 0; t < Sq; t++) {
        const int s  = dir ? (Sq - 1 - t) : t;
        const int sp = dir ? (Sq - t) : (t - 1);   // previous step's s (t>0)

        if (tid < 64) toks[tid] = tokens[(b0 + tid) * Sq + s];

        float acc[4][4];                    // [nt][quad]
#pragma unroll
        for (int nt = 0; nt < 4; nt++)
#pragma unroll
            for (int q = 0; q < 4; q++) acc[nt][q] = 0.f;

        if (t > 0) {
            auto issue_A = [&](int c, int buf) {
#pragma unroll
                for (int i = 0; i < 2; i++) {
                    int id = i * 512 + tid;        // 0..1023
                    int r = id >> 4, ch = id & 15;
                    unsigned dst = sb + buf * LP_STAGE + LP_UCH +
                                   r * LP_RS + ((unsigned)(ch ^ (r & 7)) << 4);
                    cp_async16(dst, g_Ahi +
                        ((size_t)(b0 + r) * Sq + sp) * Kout + dir * Hq +
                        c * 128 + ch * 8);
                }
            };

            // G0 = A0;  G1 = A1 + U4(stream->buf0.U)
            issue_A(0, 0); CP_COMMIT();
            issue_A(1, 1); issue_U(512, sb); CP_COMMIT();

            for (int c = 0; c < 8; c++) {
                if (c < 7) { CP_WAIT(1); } else { CP_WAIT(0); }
                __syncthreads();

                const unsigned Bbase = (c < 4)
                    ? (sb + LP_UPOFF + c * LP_UCH)
                    : (sb + (c & 1) * LP_STAGE);
                const unsigned Abase = sb + (c & 1) * LP_STAGE + LP_UCH;

#pragma unroll
                for (int kh = 0; kh < 8; kh++) {
                    const int a_row = warp_m * 16 + (lane & 15);
                    const int a_c16 = kh * 2 + (lane >> 4);
                    unsigned aH[4];
                    ldmatrix_x4(aH, Abase + a_row * LP_RS +
                                ((unsigned)((a_c16 ^ (a_row & 7))) << 4));

                    unsigned bH[4][2];
#pragma unroll
                    for (int np = 0; np < 2; np++) {
                        const int b_row = warp_n * 32 + (lane & 7) +
                                          ((lane >> 4) << 3) + np * 16;
                        const int b_c16 = kh * 2 + ((lane >> 3) & 1);
                        unsigned r4[4];
                        ldmatrix_x4(r4, Bbase + b_row * LP_RS +
                                    ((unsigned)((b_c16 ^ (b_row & 7))) << 4));
                        bH[np * 2][0] = r4[0]; bH[np * 2][1] = r4[1];
                        bH[np * 2 + 1][0] = r4[2]; bH[np * 2 + 1][1] = r4[3];
                    }

#pragma unroll
                    for (int nt = 0; nt < 4; nt++)
                        mma_f16(acc[nt], aH, bH[nt]);
                }

                __syncthreads();

                // Post-issue schedule (verified clobber/order-safe):
                if      (c == 0) { issue_A(2, 0); issue_U(640, sb + LP_STAGE); CP_COMMIT(); }
                else if (c == 1) { issue_A(3, 1); CP_COMMIT(); }
                else if (c == 2) { issue_A(4, 0); CP_COMMIT(); }
                else if (c == 3) { issue_A(5, 1); CP_COMMIT(); }
                else if (c == 4) { issue_A(6, 0); issue_U(768, sb); CP_COMMIT(); }
                else if (c == 5) { issue_A(7, 1); issue_U(896, sb + LP_STAGE); CP_COMMIT(); }
            }
        }

        __syncthreads();   // all MMA reads done; safe to alias buf0 as zs

        // fragments -> z tile
        {
            int r = warp_m * 16 + (lane >> 2);
#pragma unroll
            for (int nt = 0; nt < 4; nt++) {
                int col = warp_n * 32 + nt * 8 + 2 * (lane & 3);
                *reinterpret_cast<float2*>(&zs[r][col]) =
                    make_float2(acc[nt][0], acc[nt][1]);
                *reinterpret_cast<float2*>(&zs[r + 8][col]) =
                    make_float2(acc[nt][2], acc[nt][3]);
            }
        }
        __syncthreads();

        // fused gate update: 64 rows x 32 hidden units / 512 threads
#pragma unroll
        for (int it = 0; it < 4; it++) {
            int idx = it * 512 + tid;
            int r  = idx >> 5;     // 0..63
            int jj = idx & 31;     // 0..31
            int j = j0q + jj;

            float4 z4 = *reinterpret_cast<const float4*>(&zs[r][jj * 4]);
            int tok = toks[r];
            float4 ew = *reinterpret_cast<const float4*>(
                &embW[(size_t)tok * G4H + (j << 2)]);
            float zi = z4.x + ew.x;
            float zf = z4.y + ew.y;
            float zg = z4.z + ew.z;
            float zo = z4.w + ew.w;

            float ig = sigmoidf_fast(zi);
            float fg = sigmoidf_fast(zf);
            float og = sigmoidf_fast(zo);
            float gg = dir ? fmaxf(zg, 0.f) : tanhf(zg);

            int ci = (b0 + r) * Hq + j;
            float cv = fg * cptr[ci] + ig * gg;
            cptr[ci] = cv;
            float hc = dir ? fmaxf(cv, 0.f) : tanhf(cv);
            float hv = og * hc;

            size_t ao = ((size_t)(b0 + r) * Sq + s) * Kout + dir * Hq + j;
            g_Ahi[ao] = __float2half(hv);
        }

        // ---- 32-CTA group barrier (release/acquire, tid0 only) ----
        if (t + 1 < Sq) {
            __syncthreads();               // all epilogue STGs issued
            if (tid == 0) {
                bar_arrive_release(&g_barrier[gid]);
                unsigned tgt = 32u * (unsigned)(t + 1);
                while (bar_peek_acquire(&g_barrier[gid]) < tgt) {}
            }
            __syncthreads();               // broadcast acquire to all threads
        }
    }
}

// ---------------------------------------------------------------------------
// Launch
// ---------------------------------------------------------------------------
extern "C" void kernel_launch(void* const* d_in, const int* in_sizes, int n_in,
                              void* d_out, int out_size) {
    (void)in_sizes; (void)n_in; (void)out_size;
    const int*   tokens = (const int*)  d_in[0];
    const float* emb    = (const float*)d_in[1];
    const float* Wf     = (const float*)d_in[2];
    const float* Uf     = (const float*)d_in[3];
    const float* bf     = (const float*)d_in[4];
    const float* Wb     = (const float*)d_in[5];
    const float* Ub     = (const float*)d_in[6];
    const float* bb     = (const float*)d_in[7];
    const float* Wd     = (const float*)d_in[8];
    const float* bd     = (const float*)d_in[9];
    float* out = (float*)d_out;

    float *p_btf, *p_btb, *p_embWtf, *p_embWtb;
    __half *p_emb16, *p_Wt16f, *p_Wt16b, *p_Ahi, *p_Bhi;
    cudaGetSymbolAddress((void**)&p_btf,    g_btf);
    cudaGetSymbolAddress((void**)&p_btb,    g_btb);
    cudaGetSymbolAddress((void**)&p_embWtf, g_embWtf);
    cudaGetSymbolAddress((void**)&p_embWtb, g_embWtb);
    cudaGetSymbolAddress((void**)&p_emb16,  g_emb16);
    cudaGetSymbolAddress((void**)&p_Wt16f,  g_Wt16f);
    cudaGetSymbolAddress((void**)&p_Wt16b,  g_Wt16b);
    cudaGetSymbolAddress((void**)&p_Ahi,    g_Ahi);
    cudaGetSymbolAddress((void**)&p_Bhi,    g_Bhi);

    cudaFuncSetAttribute(hgemm_bias_kernel,
                         cudaFuncAttributeMaxDynamicSharedMemorySize, OG_SMEM);
    cudaFuncSetAttribute(lstm_persistent_kernel,
                         cudaFuncAttributeMaxDynamicSharedMemorySize, LP_SMEM);

    init_state_kernel<<<(Vq * Eq + 255) / 256, 256>>>(emb);
    interleave_b_kernel<<<(G4H + 255) / 256, 256>>>(bf, bb);
    transpose_W16_kernel<<<dim3(Hq / 32, Eq / 32, 8), dim3(32, 8)>>>(Wf, Wb);
    split_transpose_U_kernel<<<dim3(Hq / 32, Hq / 32, 8), dim3(32, 8)>>>(Uf, Ub);
    split_transpose_Wd_kernel<<<dim3(Vq / 32, Kout / 32), dim3(32, 8)>>>(Wd);

    // embWt = emb16 @ Wt16^T + bt  (gate-interleaved, bias folded), fp16 HMMA
    hgemm_bias_kernel<<<dim3(G4H / 128, Vq / 128), 256, OG_SMEM>>>(
        p_emb16, p_Wt16f, p_btf, p_embWtf, Eq, G4H);
    hgemm_bias_kernel<<<dim3(G4H / 128, Vq / 128), 256, OG_SMEM>>>(
        p_emb16, p_Wt16b, p_btb, p_embWtb, Eq, G4H);

    // ALL 256 recurrent steps in one persistent launch
    lstm_persistent_kernel<<<dim3(G4H / 128, Bq / 64, 2), 512, LP_SMEM>>>(tokens);

    // out = hcat16 @ Wd16^T + bd
    hgemm_bias_kernel<<<dim3(Vq / 128, Mout / 128), 256, OG_SMEM>>>(
        p_Ahi, p_Bhi, bd, out, Kout, Vq);
}